// round 4
// baseline (speedup 1.0000x reference)
#include <cuda_runtime.h>
#include <cuda_bf16.h>
#include <math.h>
#include <stdint.h>

// ---------------- Problem constants (fixed shapes) ----------------
#define BATCH 2
#define SEQ   2048
#define NTOK  (BATCH*SEQ)        // 4096
#define HID   2048
#define NH    16
#define DQ    192                // 128 nope + 64 rope
#define DNOPE 128
#define DROPE 64
#define DV    128
#define KVR   512
#define INTER 10944

// ---------------- Scratch (device globals; allocation-free) ----------------
__device__ float g_xln [NTOK*HID];
__device__ float g_q   [NTOK*NH*DQ];
__device__ float g_ckv [NTOK*(KVR+DROPE)];
__device__ float g_cln [NTOK*KVR];
__device__ float g_kv  [NTOK*NH*(DNOPE+DV)];
__device__ float g_qf  [BATCH*NH*SEQ*DQ];
__device__ float g_kf  [BATCH*NH*SEQ*DQ];
__device__ float g_v   [BATCH*NH*SEQ*DV];
__device__ float g_attn[NTOK*HID];
__device__ float g_x1  [NTOK*HID];
__device__ float g_y   [NTOK*HID];
__device__ float g_g   [NTOK*INTER];
__device__ float g_u   [NTOK*INTER];
// tf32-rounded weight copies
__device__ float g_wq  [NH*DQ*HID];
__device__ float g_wkva[(KVR+DROPE)*HID];
__device__ float g_wkvb[NH*(DNOPE+DV)*KVR];
__device__ float g_wo  [HID*NH*DV];
__device__ float g_wg  [INTER*HID];
__device__ float g_wu  [INTER*HID];
__device__ float g_wd  [HID*INTER];

// ---------------- tf32 round helper ----------------
__device__ __forceinline__ float f2tf32(float x) {
    asm("cvt.rna.tf32.f32 %0, %0;" : "+f"(x));
    return x;
}

// ---------------- weight pre-round (rna) ----------------
__global__ void round_tf32_kernel(const float* __restrict__ in, float* __restrict__ out, int n4) {
    int i = blockIdx.x * blockDim.x + threadIdx.x;
    if (i < n4) {
        float4 v = ((const float4*)in)[i];
        v.x = f2tf32(v.x); v.y = f2tf32(v.y); v.z = f2tf32(v.z); v.w = f2tf32(v.w);
        ((float4*)out)[i] = v;
    }
}

// ---------------- RMSNorm (output rounded to tf32: feeds GEMMs only) -------
__global__ void rmsnorm_kernel(const float* __restrict__ in, const float* __restrict__ w,
                               float* __restrict__ out, int cols, int instride) {
    int row = blockIdx.x;
    int tid = threadIdx.x;
    const float* xr = in + (size_t)row * instride;
    float s = 0.f;
    for (int c = tid; c < cols; c += 256) { float v = xr[c]; s += v * v; }
    __shared__ float red[8];
    for (int o = 16; o; o >>= 1) s += __shfl_xor_sync(0xffffffffu, s, o);
    if ((tid & 31) == 0) red[tid >> 5] = s;
    __syncthreads();
    float tot = 0.f;
    #pragma unroll
    for (int i = 0; i < 8; i++) tot += red[i];
    float inv = rsqrtf(tot / (float)cols + 1e-6f);
    for (int c = tid; c < cols; c += 256)
        out[(size_t)row * cols + c] = f2tf32(xr[c] * inv * w[c]);
}

// ---------------- TF32 tensor-core GEMM, 2-stage cp.async pipeline --------
// C[M,N] = A[M,K] @ W[N,K]^T (+R). Operands must already be tf32-rounded.
// CTA tile 128x128, BK=32, 256 threads = 8 warps (2m x 4n), warp 64x32.
// Dynamic smem: 2 stages x (128x36 A + 128x36 W) floats = 73728 bytes.
#define GEMM_SMEM (2*4608*2*4)
template<int EPI>   // 0: none, 1: add residual R[M,N]
__global__ void __launch_bounds__(256, 2)
tf32gemm_pipe(const float* __restrict__ A, const float* __restrict__ W,
              const float* __restrict__ R, float* __restrict__ C,
              int M, int N, int K) {
    extern __shared__ float smbuf[];
    float* AsB = smbuf;              // 2 stages, stride 4608 floats
    float* WsB = smbuf + 2 * 4608;

    const int tid  = threadIdx.x;
    const int warp = tid >> 5, lane = tid & 31;
    const int wm = warp >> 2;        // 0..1
    const int wn = warp & 3;         // 0..3
    const int g = lane >> 2, t = lane & 3;
    const int bm = blockIdx.y * 128;
    const int bn = blockIdx.x * 128;

    float acc[4][4][4];
    #pragma unroll
    for (int i = 0; i < 4; i++)
        #pragma unroll
        for (int j = 0; j < 4; j++)
            #pragma unroll
            for (int c = 0; c < 4; c++) acc[i][j][c] = 0.f;

    // per-thread loader mapping: 4 x 16B per tile per matrix
    int lm[4], lc[4];
    #pragma unroll
    for (int i = 0; i < 4; i++) {
        int idx = tid + 256 * i;
        lm[i] = idx >> 3;            // row 0..127
        lc[i] = (idx & 7) * 4;       // col 0,4,..,28
    }

    // ---- issue loads for stage s at k-offset k0 ----
    auto load_tile = [&](int s, int k0) {
        #pragma unroll
        for (int i = 0; i < 4; i++) {
            int m = lm[i], c4 = lc[i];
            {
                uint32_t d = (uint32_t)__cvta_generic_to_shared(&AsB[s * 4608 + m * 36 + c4]);
                const float* src = &A[(size_t)(bm + m) * K + k0 + c4];
                asm volatile("cp.async.cg.shared.global [%0], [%1], 16;" :: "r"(d), "l"(src));
            }
            {
                int n = bn + m;
                int ok = (n < N) ? 16 : 0;
                const float* src = &W[(size_t)(n < N ? n : N - 1) * K + k0 + c4];
                uint32_t d = (uint32_t)__cvta_generic_to_shared(&WsB[s * 4608 + m * 36 + c4]);
                asm volatile("cp.async.cg.shared.global [%0], [%1], 16, %2;"
                             :: "r"(d), "l"(src), "r"(ok));
            }
        }
    };

    load_tile(0, 0);
    asm volatile("cp.async.commit_group;" ::: "memory");

    int s = 0;
    for (int k0 = 0; k0 < K; k0 += 32, s ^= 1) {
        asm volatile("cp.async.wait_group 0;" ::: "memory");
        __syncthreads();
        if (k0 + 32 < K) {
            load_tile(s ^ 1, k0 + 32);
            asm volatile("cp.async.commit_group;" ::: "memory");
        }
        const float* Ab = &AsB[s * 4608];
        const float* Wb = &WsB[s * 4608];
        #pragma unroll
        for (int ks = 0; ks < 4; ks++) {
            int kk = ks * 8;
            uint32_t af[4][4];
            #pragma unroll
            for (int i = 0; i < 4; i++) {
                int r = wm * 64 + i * 16 + g;
                af[i][0] = __float_as_uint(Ab[(r    ) * 36 + kk + t    ]);
                af[i][1] = __float_as_uint(Ab[(r + 8) * 36 + kk + t    ]);
                af[i][2] = __float_as_uint(Ab[(r    ) * 36 + kk + t + 4]);
                af[i][3] = __float_as_uint(Ab[(r + 8) * 36 + kk + t + 4]);
            }
            uint32_t bf[4][2];
            #pragma unroll
            for (int j = 0; j < 4; j++) {
                int n = wn * 32 + j * 8 + g;
                bf[j][0] = __float_as_uint(Wb[n * 36 + kk + t    ]);
                bf[j][1] = __float_as_uint(Wb[n * 36 + kk + t + 4]);
            }
            #pragma unroll
            for (int i = 0; i < 4; i++)
                #pragma unroll
                for (int j = 0; j < 4; j++) {
                    asm volatile(
                        "mma.sync.aligned.m16n8k8.row.col.f32.tf32.tf32.f32 "
                        "{%0,%1,%2,%3}, {%4,%5,%6,%7}, {%8,%9}, {%0,%1,%2,%3};"
                        : "+f"(acc[i][j][0]), "+f"(acc[i][j][1]),
                          "+f"(acc[i][j][2]), "+f"(acc[i][j][3])
                        : "r"(af[i][0]), "r"(af[i][1]), "r"(af[i][2]), "r"(af[i][3]),
                          "r"(bf[j][0]), "r"(bf[j][1]));
                }
        }
        __syncthreads();
    }

    // ---- epilogue ----
    #pragma unroll
    for (int i = 0; i < 4; i++) {
        int r0 = bm + wm * 64 + i * 16 + g;
        #pragma unroll
        for (int j = 0; j < 4; j++) {
            int c = bn + wn * 32 + j * 8 + 2 * t;
            if (c < N) {
                float2 v0 = make_float2(acc[i][j][0], acc[i][j][1]);
                float2 v1 = make_float2(acc[i][j][2], acc[i][j][3]);
                if (EPI == 1) {
                    float2 r = *(const float2*)&R[(size_t)r0 * N + c];
                    v0.x += r.x; v0.y += r.y;
                    float2 r2 = *(const float2*)&R[(size_t)(r0 + 8) * N + c];
                    v1.x += r2.x; v1.y += r2.y;
                }
                *(float2*)&C[(size_t)r0 * N + c]       = v0;
                *(float2*)&C[(size_t)(r0 + 8) * N + c] = v1;
            }
        }
    }
}

// ---------------- RoPE (yarn) helpers ----------------
__device__ __forceinline__ void yarn_cossin(int j, int pos, float& c, float& s) {
    float ar = (float)j * (1.0f / 32.0f);
    float fe = __powf(10000.0f, -ar);
    float fi = fe * (1.0f / 40.0f);
    float ramp = fminf(fmaxf(((float)j - 10.0f) * (1.0f / 13.0f), 0.0f), 1.0f);
    float f = fi * ramp + fe * (1.0f - ramp);
    float a = (float)pos * f;
    c = cosf(a); s = sinf(a);
}

// q [NTOK, NH*DQ] -> qf [B,H,S,DQ] with rope on last 64 (deinterleaved)
__global__ void build_qf(const float* __restrict__ q, const int* __restrict__ pos_ids,
                         float* __restrict__ qf) {
    int t = blockIdx.x;
    int b = t / SEQ, s = t % SEQ;
    int tid = threadIdx.x;              // 128
    __shared__ float cs[32], sn[32];
    int pos = pos_ids[t];
    if (tid < 32) yarn_cossin(tid, pos, cs[tid], sn[tid]);
    __syncthreads();
    for (int h = 0; h < NH; h++) {
        size_t src = (size_t)t * (NH * DQ) + h * DQ;
        size_t dst = ((size_t)(b * NH + h) * SEQ + s) * DQ;
        qf[dst + tid] = q[src + tid];
        if (tid < 32) {
            float p0 = q[src + DNOPE + 2 * tid];
            float p1 = q[src + DNOPE + 2 * tid + 1];
            qf[dst + DNOPE + tid]      = p0 * cs[tid] - p1 * sn[tid];
            qf[dst + DNOPE + 32 + tid] = p1 * cs[tid] + p0 * sn[tid];
        }
    }
}

// kv [NTOK, NH*256], ckv [NTOK, 576] -> kf [B,H,S,192], v [B,H,S,128]
__global__ void build_kf(const float* __restrict__ kv, const float* __restrict__ ckv,
                         const int* __restrict__ pos_ids,
                         float* __restrict__ kf, float* __restrict__ vv) {
    int t = blockIdx.x;
    int b = t / SEQ, s = t % SEQ;
    int tid = threadIdx.x;              // 128
    __shared__ float cs[32], sn[32], kr[64];
    int pos = pos_ids[t];
    if (tid < 32) yarn_cossin(tid, pos, cs[tid], sn[tid]);
    __syncthreads();
    if (tid < 32) {
        float p0 = ckv[(size_t)t * (KVR + DROPE) + KVR + 2 * tid];
        float p1 = ckv[(size_t)t * (KVR + DROPE) + KVR + 2 * tid + 1];
        kr[tid]      = p0 * cs[tid] - p1 * sn[tid];
        kr[tid + 32] = p1 * cs[tid] + p0 * sn[tid];
    }
    __syncthreads();
    for (int h = 0; h < NH; h++) {
        size_t src = (size_t)t * (NH * 256) + h * 256;
        size_t d0 = ((size_t)(b * NH + h) * SEQ + s);
        kf[d0 * DQ + tid] = kv[src + tid];
        vv[d0 * DV + tid] = kv[src + DNOPE + tid];
        if (tid < 64) kf[d0 * DQ + DNOPE + tid] = kr[tid];
    }
}

// ---------------- Causal attention, online softmax ----------------
// output rounded to tf32 (feeds the Wo GEMM only)
__global__ void __launch_bounds__(256)
attn_kernel(const float* __restrict__ qf, const float* __restrict__ kf,
            const float* __restrict__ vv, float* __restrict__ out) {
    __shared__ float qs[16][196];
    __shared__ float ks[16][196];
    __shared__ float vs[16][128];
    __shared__ float lg[16][16];
    int tid = threadIdx.x;
    int q16 = tid >> 4, x16 = tid & 15;
    int b = blockIdx.z, h = blockIdx.y;
    int q0 = blockIdx.x * 16;
    size_t bqk = (size_t)(b * NH + h) * SEQ * DQ;
    size_t bv  = (size_t)(b * NH + h) * SEQ * DV;

    for (int i = tid; i < 16 * 48; i += 256) {
        int r = i / 48, c4 = i % 48;
        *(float4*)&qs[r][c4 * 4] = *(const float4*)&qf[bqk + (size_t)(q0 + r) * DQ + c4 * 4];
    }
    float acc[8];
    #pragma unroll
    for (int j = 0; j < 8; j++) acc[j] = 0.f;
    float m = -INFINITY, l = 0.f;
    int myq = q0 + q16;
    const float scale = 0.07216878364870323f;    // 192^-0.5

    for (int kc = 0; kc < q0 + 16; kc += 16) {
        __syncthreads();
        for (int i = tid; i < 16 * 48; i += 256) {
            int r = i / 48, c4 = i % 48;
            *(float4*)&ks[r][c4 * 4] = *(const float4*)&kf[bqk + (size_t)(kc + r) * DQ + c4 * 4];
        }
        for (int i = tid; i < 16 * 32; i += 256) {
            int r = i / 32, c4 = i % 32;
            *(float4*)&vs[r][c4 * 4] = *(const float4*)&vv[bv + (size_t)(kc + r) * DV + c4 * 4];
        }
        __syncthreads();
        float dot = 0.f;
        #pragma unroll 8
        for (int d = 0; d < DQ; d += 4) {
            float4 a = *(const float4*)&qs[q16][d];
            float4 k4 = *(const float4*)&ks[x16][d];
            dot += a.x * k4.x + a.y * k4.y + a.z * k4.z + a.w * k4.w;
        }
        lg[q16][x16] = (kc + x16 <= myq) ? dot * scale : -INFINITY;
        __syncthreads();
        float cmax = -INFINITY;
        #pragma unroll
        for (int k = 0; k < 16; k++) cmax = fmaxf(cmax, lg[q16][k]);
        float nm = fmaxf(m, cmax);
        float corr = __expf(m - nm);
        l *= corr;
        #pragma unroll
        for (int j = 0; j < 8; j++) acc[j] *= corr;
        #pragma unroll
        for (int k = 0; k < 16; k++) {
            float p = __expf(lg[q16][k] - nm);
            l += p;
            const float* vr = &vs[k][x16 * 8];
            #pragma unroll
            for (int j = 0; j < 8; j++) acc[j] += p * vr[j];
        }
        m = nm;
    }
    float inv = 1.0f / l;
    size_t o = ((size_t)(b * SEQ + myq)) * (NH * DV) + h * DV + x16 * 8;
    #pragma unroll
    for (int j = 0; j < 8; j++) out[o + j] = f2tf32(acc[j] * inv);
}

// ---------------- SiLU(g)*u, in place into g (rounded: feeds Wd GEMM) -----
__global__ void silu_mul(float* __restrict__ g, const float* __restrict__ u, size_t n) {
    for (size_t i = (size_t)blockIdx.x * blockDim.x + threadIdx.x; i < n;
         i += (size_t)gridDim.x * blockDim.x) {
        float x = g[i];
        g[i] = f2tf32(x / (1.0f + __expf(-x)) * u[i]);
    }
}

// ---------------- Launch ----------------
extern "C" void kernel_launch(void* const* d_in, const int* in_sizes, int n_in,
                              void* d_out, int out_size) {
    const float* hidden = (const float*)d_in[0];
    const int*   pos    = (const int*)d_in[1];
    const float* Wq     = (const float*)d_in[2];
    const float* Wkva   = (const float*)d_in[3];
    const float* w_kvln = (const float*)d_in[4];
    const float* Wkvb   = (const float*)d_in[5];
    const float* Wo     = (const float*)d_in[6];
    const float* Wg     = (const float*)d_in[7];
    const float* Wu     = (const float*)d_in[8];
    const float* Wd     = (const float*)d_in[9];
    const float* w_ln1  = (const float*)d_in[10];
    const float* w_ln2  = (const float*)d_in[11];
    float* out = (float*)d_out;

    float *xln, *q, *ckv, *cln, *kv, *qfp, *kfp, *vp, *attn, *x1, *y, *gg, *uu;
    float *wq, *wkva, *wkvb, *wo, *wg, *wu, *wd;
    cudaGetSymbolAddress((void**)&xln,  g_xln);
    cudaGetSymbolAddress((void**)&q,    g_q);
    cudaGetSymbolAddress((void**)&ckv,  g_ckv);
    cudaGetSymbolAddress((void**)&cln,  g_cln);
    cudaGetSymbolAddress((void**)&kv,   g_kv);
    cudaGetSymbolAddress((void**)&qfp,  g_qf);
    cudaGetSymbolAddress((void**)&kfp,  g_kf);
    cudaGetSymbolAddress((void**)&vp,   g_v);
    cudaGetSymbolAddress((void**)&attn, g_attn);
    cudaGetSymbolAddress((void**)&x1,   g_x1);
    cudaGetSymbolAddress((void**)&y,    g_y);
    cudaGetSymbolAddress((void**)&gg,   g_g);
    cudaGetSymbolAddress((void**)&uu,   g_u);
    cudaGetSymbolAddress((void**)&wq,   g_wq);
    cudaGetSymbolAddress((void**)&wkva, g_wkva);
    cudaGetSymbolAddress((void**)&wkvb, g_wkvb);
    cudaGetSymbolAddress((void**)&wo,   g_wo);
    cudaGetSymbolAddress((void**)&wg,   g_wg);
    cudaGetSymbolAddress((void**)&wu,   g_wu);
    cudaGetSymbolAddress((void**)&wd,   g_wd);

    cudaFuncSetAttribute(tf32gemm_pipe<0>, cudaFuncAttributeMaxDynamicSharedMemorySize, GEMM_SMEM);
    cudaFuncSetAttribute(tf32gemm_pipe<1>, cudaFuncAttributeMaxDynamicSharedMemorySize, GEMM_SMEM);

    dim3 blk(256);
    // 0. pre-round weights to tf32 (rna) once per replay
    {
        struct { const float* s; float* d; int n; } ws[7] = {
            {Wq,   wq,   NH*DQ*HID}, {Wkva, wkva, (KVR+DROPE)*HID},
            {Wkvb, wkvb, NH*(DNOPE+DV)*KVR}, {Wo, wo, HID*NH*DV},
            {Wg,   wg,   INTER*HID}, {Wu, wu, INTER*HID}, {Wd, wd, HID*INTER}
        };
        for (int i = 0; i < 7; i++) {
            int n4 = ws[i].n / 4;
            round_tf32_kernel<<<(n4 + 255) / 256, 256>>>(ws[i].s, ws[i].d, n4);
        }
    }
    // 1. ln1 (output tf32-rounded)
    rmsnorm_kernel<<<NTOK, blk>>>(hidden, w_ln1, xln, HID, HID);
    // 2. q = xln @ Wq^T   [4096 x 3072] K=2048
    tf32gemm_pipe<0><<<dim3((NH * DQ + 127) / 128, NTOK / 128), blk, GEMM_SMEM>>>(xln, wq, nullptr, q, NTOK, NH * DQ, HID);
    // 3. ckv = xln @ Wkva^T  [4096 x 576] K=2048
    tf32gemm_pipe<0><<<dim3((KVR + DROPE + 127) / 128, NTOK / 128), blk, GEMM_SMEM>>>(xln, wkva, nullptr, ckv, NTOK, KVR + DROPE, HID);
    // 4. c_ln = rms(ckv[:, :512]) * w_kvln (rounded)
    rmsnorm_kernel<<<NTOK, blk>>>(ckv, w_kvln, cln, KVR, KVR + DROPE);
    // 5. kv = c_ln @ Wkvb^T  [4096 x 4096] K=512
    tf32gemm_pipe<0><<<dim3((NH * 256) / 128, NTOK / 128), blk, GEMM_SMEM>>>(cln, wkvb, nullptr, kv, NTOK, NH * 256, KVR);
    // 6/7. layouts + rope
    build_qf<<<NTOK, 128>>>(q, pos, qfp);
    build_kf<<<NTOK, 128>>>(kv, ckv, pos, kfp, vp);
    // 8. attention (output rounded)
    attn_kernel<<<dim3(SEQ / 16, NH, BATCH), blk>>>(qfp, kfp, vp, attn);
    // 9. x1 = hidden + attn @ Wo^T  K=2048
    tf32gemm_pipe<1><<<dim3(HID / 128, NTOK / 128), blk, GEMM_SMEM>>>(attn, wo, hidden, x1, NTOK, HID, NH * DV);
    // 10. y = rms(x1) * w_ln2 (rounded)
    rmsnorm_kernel<<<NTOK, blk>>>(x1, w_ln2, y, HID, HID);
    // 11. g = y @ Wg^T, u = y @ Wu^T  [4096 x 10944] K=2048
    tf32gemm_pipe<0><<<dim3((INTER + 127) / 128, NTOK / 128), blk, GEMM_SMEM>>>(y, wg, nullptr, gg, NTOK, INTER, HID);
    tf32gemm_pipe<0><<<dim3((INTER + 127) / 128, NTOK / 128), blk, GEMM_SMEM>>>(y, wu, nullptr, uu, NTOK, INTER, HID);
    // 12. g = silu(g) * u (rounded)
    silu_mul<<<4096, blk>>>(gg, uu, (size_t)NTOK * INTER);
    // 13. out = x1 + g @ Wd^T  K=10944
    tf32gemm_pipe<1><<<dim3(HID / 128, NTOK / 128), blk, GEMM_SMEM>>>(gg, wd, x1, out, NTOK, HID, INTER);
}

// round 6
// speedup vs baseline: 1.1398x; 1.1398x over previous
#include <cuda_runtime.h>
#include <cuda_bf16.h>
#include <math.h>
#include <stdint.h>

// ---------------- Problem constants (fixed shapes) ----------------
#define BATCH 2
#define SEQ   2048
#define NTOK  (BATCH*SEQ)        // 4096
#define HID   2048
#define NH    16
#define DQ    192
#define DNOPE 128
#define DROPE 64
#define DV    128
#define KVR   512
#define INTER 10944

// ---------------- Scratch (device globals; allocation-free) ----------------
__device__ float g_xln [NTOK*HID];
__device__ float g_q   [NTOK*NH*DQ];
__device__ float g_ckv [NTOK*(KVR+DROPE)];
__device__ float g_cln [NTOK*KVR];
__device__ float g_kv  [NTOK*NH*(DNOPE+DV)];
__device__ float g_qf  [BATCH*NH*SEQ*DQ];
__device__ float g_kf  [BATCH*NH*SEQ*DQ];
__device__ float g_v   [BATCH*NH*SEQ*DV];
__device__ float g_attn[NTOK*HID];
__device__ float g_x1  [NTOK*HID];
__device__ float g_y   [NTOK*HID];
__device__ float g_g   [NTOK*INTER];
__device__ float g_u   [NTOK*INTER];

// ---------------- helpers ----------------
__device__ __forceinline__ float f2tf32(float x) {
    asm("cvt.rna.tf32.f32 %0, %0;" : "+f"(x));
    return x;
}

// ---------------- RMSNorm (output rounded to tf32: feeds GEMMs) ----------
__global__ void rmsnorm_kernel(const float* __restrict__ in, const float* __restrict__ w,
                               float* __restrict__ out, int cols, int instride) {
    int row = blockIdx.x;
    int tid = threadIdx.x;
    const float* xr = in + (size_t)row * instride;
    float s = 0.f;
    for (int c = tid; c < cols; c += 256) { float v = xr[c]; s += v * v; }
    __shared__ float red[8];
    for (int o = 16; o; o >>= 1) s += __shfl_xor_sync(0xffffffffu, s, o);
    if ((tid & 31) == 0) red[tid >> 5] = s;
    __syncthreads();
    float tot = 0.f;
    #pragma unroll
    for (int i = 0; i < 8; i++) tot += red[i];
    float inv = rsqrtf(tot / (float)cols + 1e-6f);
    for (int c = tid; c < cols; c += 256)
        out[(size_t)row * cols + c] = f2tf32(xr[c] * inv * w[c]);
}

// ---------------- TF32 mma.sync GEMM, 64x64 warp tiles --------------------
// C[M,N] = A[M,K] @ W[N,K]^T (+R).  A must be tf32-pre-rounded (producers do
// rna); W is raw fp32, rounded in-kernel (rna) during the smem store.
// CTA 128x128, BK=32, 128 threads = 4 warps (2m x 2n), warp tile 64x64.
// A: 2-stage cp.async pipeline. W: LDG->reg prefetch -> cvt+STS.
// Requirements: M % 128 == 0, K % 32 == 0, N arbitrary (guarded).
#define GEMM_SMEM (2*4608*2*4)    // 2 stages x (A 128x36 + W 128x36) floats
template<int EPI>   // 0: none, 1: add residual R[M,N]
__global__ void __launch_bounds__(128, 2)
tf32gemm(const float* __restrict__ A, const float* __restrict__ W,
         const float* __restrict__ R, float* __restrict__ C,
         int M, int N, int K) {
    extern __shared__ float smbuf[];
    float* AsB = smbuf;              // 2 stages, stride 4608 floats
    float* WsB = smbuf + 2 * 4608;

    const int tid  = threadIdx.x;
    const int warp = tid >> 5, lane = tid & 31;
    const int wm = warp >> 1;        // 0..1 -> 64 rows
    const int wn = warp & 1;         // 0..1 -> 64 cols
    const int g = lane >> 2, t = lane & 3;
    const int bm = blockIdx.y * 128;
    const int bn = blockIdx.x * 128;

    float acc[4][8][4];
    #pragma unroll
    for (int i = 0; i < 4; i++)
        #pragma unroll
        for (int j = 0; j < 8; j++)
            #pragma unroll
            for (int c = 0; c < 4; c++) acc[i][j][c] = 0.f;

    // loader mapping: 8 x float4 per matrix per tile per thread
    const int lrow = tid >> 3;              // used with +16*i? no: ch scheme below
    (void)lrow;

    // ---- A loader: cp.async 8 chunks ----
    auto load_A = [&](int s, int k0) {
        #pragma unroll
        for (int i = 0; i < 8; i++) {
            int ch = tid + 128 * i;          // 0..1023
            int m = ch >> 3, c4 = (ch & 7) * 4;
            uint32_t d = (uint32_t)__cvta_generic_to_shared(&AsB[s * 4608 + m * 36 + c4]);
            const float* src = &A[(size_t)(bm + m) * K + k0 + c4];
            asm volatile("cp.async.cg.shared.global [%0], [%1], 16;" :: "r"(d), "l"(src));
        }
        asm volatile("cp.async.commit_group;" ::: "memory");
    };
    // ---- W loader: LDG into regs ----
    auto ldg_W = [&](int k0, float4* wreg) {
        #pragma unroll
        for (int i = 0; i < 8; i++) {
            int ch = tid + 128 * i;
            int n = bn + (ch >> 3), c4 = (ch & 7) * 4;
            const float* src = &W[(size_t)(n < N ? n : 0) * K + k0 + c4];
            wreg[i] = *(const float4*)src;
        }
    };
    auto sts_W = [&](int s, const float4* wreg) {
        #pragma unroll
        for (int i = 0; i < 8; i++) {
            int ch = tid + 128 * i;
            int n = ch >> 3, c4 = (ch & 7) * 4;
            float4 v = wreg[i];
            v.x = f2tf32(v.x); v.y = f2tf32(v.y); v.z = f2tf32(v.z); v.w = f2tf32(v.w);
            *(float4*)&WsB[s * 4608 + n * 36 + c4] = v;
        }
    };

    auto compute = [&](int s) {
        const float* Ab = &AsB[s * 4608];
        const float* Wb = &WsB[s * 4608];
        #pragma unroll
        for (int ks = 0; ks < 4; ks++) {
            int kk = ks * 8;
            uint32_t af[4][4];
            #pragma unroll
            for (int i = 0; i < 4; i++) {
                int r = wm * 64 + i * 16 + g;
                af[i][0] = __float_as_uint(Ab[(r    ) * 36 + kk + t    ]);
                af[i][1] = __float_as_uint(Ab[(r + 8) * 36 + kk + t    ]);
                af[i][2] = __float_as_uint(Ab[(r    ) * 36 + kk + t + 4]);
                af[i][3] = __float_as_uint(Ab[(r + 8) * 36 + kk + t + 4]);
            }
            uint32_t bf[8][2];
            #pragma unroll
            for (int j = 0; j < 8; j++) {
                int n = wn * 64 + j * 8 + g;
                bf[j][0] = __float_as_uint(Wb[n * 36 + kk + t    ]);
                bf[j][1] = __float_as_uint(Wb[n * 36 + kk + t + 4]);
            }
            #pragma unroll
            for (int i = 0; i < 4; i++)
                #pragma unroll
                for (int j = 0; j < 8; j++) {
                    asm volatile(
                        "mma.sync.aligned.m16n8k8.row.col.f32.tf32.tf32.f32 "
                        "{%0,%1,%2,%3}, {%4,%5,%6,%7}, {%8,%9}, {%0,%1,%2,%3};"
                        : "+f"(acc[i][j][0]), "+f"(acc[i][j][1]),
                          "+f"(acc[i][j][2]), "+f"(acc[i][j][3])
                        : "r"(af[i][0]), "r"(af[i][1]), "r"(af[i][2]), "r"(af[i][3]),
                          "r"(bf[j][0]), "r"(bf[j][1]));
                }
        }
    };

    // ---- prologue: fill stage 0 ----
    float4 wreg[8];
    load_A(0, 0);
    ldg_W(0, wreg);
    asm volatile("cp.async.wait_group 0;" ::: "memory");
    __syncthreads();
    sts_W(0, wreg);
    __syncthreads();

    const int NK = K >> 5;
    for (int i = 0; i < NK; i++) {
        int s = i & 1;
        if (i + 1 < NK) {
            load_A(s ^ 1, (i + 1) * 32);
            ldg_W((i + 1) * 32, wreg);
        }
        compute(s);
        if (i + 1 < NK) {
            asm volatile("cp.async.wait_group 0;" ::: "memory");
            __syncthreads();
            sts_W(s ^ 1, wreg);
            __syncthreads();
        }
    }

    // ---- epilogue ----
    #pragma unroll
    for (int i = 0; i < 4; i++) {
        int r0 = bm + wm * 64 + i * 16 + g;
        #pragma unroll
        for (int j = 0; j < 8; j++) {
            int c = bn + wn * 64 + j * 8 + 2 * t;
            if (c < N) {
                float2 v0 = make_float2(acc[i][j][0], acc[i][j][1]);
                float2 v1 = make_float2(acc[i][j][2], acc[i][j][3]);
                if (EPI == 1) {
                    float2 r = *(const float2*)&R[(size_t)r0 * N + c];
                    v0.x += r.x; v0.y += r.y;
                    float2 r2 = *(const float2*)&R[(size_t)(r0 + 8) * N + c];
                    v1.x += r2.x; v1.y += r2.y;
                }
                *(float2*)&C[(size_t)r0 * N + c]       = v0;
                *(float2*)&C[(size_t)(r0 + 8) * N + c] = v1;
            }
        }
    }
}

// ---------------- RoPE (yarn) helpers ----------------
__device__ __forceinline__ void yarn_cossin(int j, int pos, float& c, float& s) {
    float ar = (float)j * (1.0f / 32.0f);
    float fe = __powf(10000.0f, -ar);
    float fi = fe * (1.0f / 40.0f);
    float ramp = fminf(fmaxf(((float)j - 10.0f) * (1.0f / 13.0f), 0.0f), 1.0f);
    float f = fi * ramp + fe * (1.0f - ramp);
    float a = (float)pos * f;
    c = cosf(a); s = sinf(a);
}

// q [NTOK, NH*DQ] -> qf [B,H,S,DQ] with rope on last 64 (deinterleaved)
__global__ void build_qf(const float* __restrict__ q, const int* __restrict__ pos_ids,
                         float* __restrict__ qf) {
    int t = blockIdx.x;
    int b = t / SEQ, s = t % SEQ;
    int tid = threadIdx.x;              // 128
    __shared__ float cs[32], sn[32];
    int pos = pos_ids[t];
    if (tid < 32) yarn_cossin(tid, pos, cs[tid], sn[tid]);
    __syncthreads();
    for (int h = 0; h < NH; h++) {
        size_t src = (size_t)t * (NH * DQ) + h * DQ;
        size_t dst = ((size_t)(b * NH + h) * SEQ + s) * DQ;
        qf[dst + tid] = q[src + tid];
        if (tid < 32) {
            float p0 = q[src + DNOPE + 2 * tid];
            float p1 = q[src + DNOPE + 2 * tid + 1];
            qf[dst + DNOPE + tid]      = p0 * cs[tid] - p1 * sn[tid];
            qf[dst + DNOPE + 32 + tid] = p1 * cs[tid] + p0 * sn[tid];
        }
    }
}

// kv [NTOK, NH*256], ckv [NTOK, 576] -> kf [B,H,S,192], v [B,H,S,128]
__global__ void build_kf(const float* __restrict__ kv, const float* __restrict__ ckv,
                         const int* __restrict__ pos_ids,
                         float* __restrict__ kf, float* __restrict__ vv) {
    int t = blockIdx.x;
    int b = t / SEQ, s = t % SEQ;
    int tid = threadIdx.x;              // 128
    __shared__ float cs[32], sn[32], kr[64];
    int pos = pos_ids[t];
    if (tid < 32) yarn_cossin(tid, pos, cs[tid], sn[tid]);
    __syncthreads();
    if (tid < 32) {
        float p0 = ckv[(size_t)t * (KVR + DROPE) + KVR + 2 * tid];
        float p1 = ckv[(size_t)t * (KVR + DROPE) + KVR + 2 * tid + 1];
        kr[tid]      = p0 * cs[tid] - p1 * sn[tid];
        kr[tid + 32] = p1 * cs[tid] + p0 * sn[tid];
    }
    __syncthreads();
    for (int h = 0; h < NH; h++) {
        size_t src = (size_t)t * (NH * 256) + h * 256;
        size_t d0 = ((size_t)(b * NH + h) * SEQ + s);
        kf[d0 * DQ + tid] = kv[src + tid];
        vv[d0 * DV + tid] = kv[src + DNOPE + tid];
        if (tid < 64) kf[d0 * DQ + DNOPE + tid] = kr[tid];
    }
}

// ---------------- Causal attention, online softmax ----------------
__global__ void __launch_bounds__(256)
attn_kernel(const float* __restrict__ qf, const float* __restrict__ kf,
            const float* __restrict__ vv, float* __restrict__ out) {
    __shared__ float qs[16][196];
    __shared__ float ks[16][196];
    __shared__ float vs[16][128];
    __shared__ float lg[16][16];
    int tid = threadIdx.x;
    int q16 = tid >> 4, x16 = tid & 15;
    int b = blockIdx.z, h = blockIdx.y;
    int q0 = blockIdx.x * 16;
    size_t bqk = (size_t)(b * NH + h) * SEQ * DQ;
    size_t bv  = (size_t)(b * NH + h) * SEQ * DV;

    for (int i = tid; i < 16 * 48; i += 256) {
        int r = i / 48, c4 = i % 48;
        *(float4*)&qs[r][c4 * 4] = *(const float4*)&qf[bqk + (size_t)(q0 + r) * DQ + c4 * 4];
    }
    float acc[8];
    #pragma unroll
    for (int j = 0; j < 8; j++) acc[j] = 0.f;
    float m = -INFINITY, l = 0.f;
    int myq = q0 + q16;
    const float scale = 0.07216878364870323f;    // 192^-0.5

    for (int kc = 0; kc < q0 + 16; kc += 16) {
        __syncthreads();
        for (int i = tid; i < 16 * 48; i += 256) {
            int r = i / 48, c4 = i % 48;
            *(float4*)&ks[r][c4 * 4] = *(const float4*)&kf[bqk + (size_t)(kc + r) * DQ + c4 * 4];
        }
        for (int i = tid; i < 16 * 32; i += 256) {
            int r = i / 32, c4 = i % 32;
            *(float4*)&vs[r][c4 * 4] = *(const float4*)&vv[bv + (size_t)(kc + r) * DV + c4 * 4];
        }
        __syncthreads();
        float dot = 0.f;
        #pragma unroll 8
        for (int d = 0; d < DQ; d += 4) {
            float4 a = *(const float4*)&qs[q16][d];
            float4 k4 = *(const float4*)&ks[x16][d];
            dot += a.x * k4.x + a.y * k4.y + a.z * k4.z + a.w * k4.w;
        }
        lg[q16][x16] = (kc + x16 <= myq) ? dot * scale : -INFINITY;
        __syncthreads();
        float cmax = -INFINITY;
        #pragma unroll
        for (int k = 0; k < 16; k++) cmax = fmaxf(cmax, lg[q16][k]);
        float nm = fmaxf(m, cmax);
        float corr = __expf(m - nm);
        l *= corr;
        #pragma unroll
        for (int j = 0; j < 8; j++) acc[j] *= corr;
        #pragma unroll
        for (int k = 0; k < 16; k++) {
            float p = __expf(lg[q16][k] - nm);
            l += p;
            const float* vr = &vs[k][x16 * 8];
            #pragma unroll
            for (int j = 0; j < 8; j++) acc[j] += p * vr[j];
        }
        m = nm;
    }
    float inv = 1.0f / l;
    size_t o = ((size_t)(b * SEQ + myq)) * (NH * DV) + h * DV + x16 * 8;
    #pragma unroll
    for (int j = 0; j < 8; j++) out[o + j] = f2tf32(acc[j] * inv);
}

// ---------------- SiLU(g)*u, in place into g (rounded: feeds Wd GEMM) ----
__global__ void silu_mul(float* __restrict__ g, const float* __restrict__ u, size_t n) {
    for (size_t i = (size_t)blockIdx.x * blockDim.x + threadIdx.x; i < n;
         i += (size_t)gridDim.x * blockDim.x) {
        float x = g[i];
        g[i] = f2tf32(x / (1.0f + __expf(-x)) * u[i]);
    }
}

// ---------------- Launch ----------------
extern "C" void kernel_launch(void* const* d_in, const int* in_sizes, int n_in,
                              void* d_out, int out_size) {
    const float* hidden = (const float*)d_in[0];
    const int*   pos    = (const int*)d_in[1];
    const float* Wq     = (const float*)d_in[2];
    const float* Wkva   = (const float*)d_in[3];
    const float* w_kvln = (const float*)d_in[4];
    const float* Wkvb   = (const float*)d_in[5];
    const float* Wo     = (const float*)d_in[6];
    const float* Wg     = (const float*)d_in[7];
    const float* Wu     = (const float*)d_in[8];
    const float* Wd     = (const float*)d_in[9];
    const float* w_ln1  = (const float*)d_in[10];
    const float* w_ln2  = (const float*)d_in[11];
    float* out = (float*)d_out;

    float *xln, *q, *ckv, *cln, *kv, *qfp, *kfp, *vp, *attn, *x1, *y, *gg, *uu;
    cudaGetSymbolAddress((void**)&xln,  g_xln);
    cudaGetSymbolAddress((void**)&q,    g_q);
    cudaGetSymbolAddress((void**)&ckv,  g_ckv);
    cudaGetSymbolAddress((void**)&cln,  g_cln);
    cudaGetSymbolAddress((void**)&kv,   g_kv);
    cudaGetSymbolAddress((void**)&qfp,  g_qf);
    cudaGetSymbolAddress((void**)&kfp,  g_kf);
    cudaGetSymbolAddress((void**)&vp,   g_v);
    cudaGetSymbolAddress((void**)&attn, g_attn);
    cudaGetSymbolAddress((void**)&x1,   g_x1);
    cudaGetSymbolAddress((void**)&y,    g_y);
    cudaGetSymbolAddress((void**)&gg,   g_g);
    cudaGetSymbolAddress((void**)&uu,   g_u);

    cudaFuncSetAttribute(tf32gemm<0>, cudaFuncAttributeMaxDynamicSharedMemorySize, GEMM_SMEM);
    cudaFuncSetAttribute(tf32gemm<1>, cudaFuncAttributeMaxDynamicSharedMemorySize, GEMM_SMEM);

    dim3 blk(256);
    // 1. ln1 (output tf32-rounded)
    rmsnorm_kernel<<<NTOK, blk>>>(hidden, w_ln1, xln, HID, HID);
    // 2. q = xln @ Wq^T   [4096 x 3072] K=2048
    tf32gemm<0><<<dim3(24, 32), 128, GEMM_SMEM>>>(xln, Wq, nullptr, q, NTOK, NH * DQ, HID);
    // 3. ckv = xln @ Wkva^T  [4096 x 576] K=2048
    tf32gemm<0><<<dim3(5, 32), 128, GEMM_SMEM>>>(xln, Wkva, nullptr, ckv, NTOK, KVR + DROPE, HID);
    // 4. c_ln = rms(ckv[:, :512]) * w_kvln (rounded)
    rmsnorm_kernel<<<NTOK, blk>>>(ckv, w_kvln, cln, KVR, KVR + DROPE);
    // 5. kv = c_ln @ Wkvb^T  [4096 x 4096] K=512
    tf32gemm<0><<<dim3(32, 32), 128, GEMM_SMEM>>>(cln, Wkvb, nullptr, kv, NTOK, NH * 256, KVR);
    // 6/7. layouts + rope
    build_qf<<<NTOK, 128>>>(q, pos, qfp);
    build_kf<<<NTOK, 128>>>(kv, ckv, pos, kfp, vp);
    // 8. attention (output rounded)
    attn_kernel<<<dim3(SEQ / 16, NH, BATCH), blk>>>(qfp, kfp, vp, attn);
    // 9. x1 = hidden + attn @ Wo^T  K=2048
    tf32gemm<1><<<dim3(16, 32), 128, GEMM_SMEM>>>(attn, Wo, hidden, x1, NTOK, HID, NH * DV);
    // 10. y = rms(x1) * w_ln2 (rounded)
    rmsnorm_kernel<<<NTOK, blk>>>(x1, w_ln2, y, HID, HID);
    // 11. g = y @ Wg^T, u = y @ Wu^T  [4096 x 10944] K=2048
    tf32gemm<0><<<dim3(86, 32), 128, GEMM_SMEM>>>(y, Wg, nullptr, gg, NTOK, INTER, HID);
    tf32gemm<0><<<dim3(86, 32), 128, GEMM_SMEM>>>(y, Wu, nullptr, uu, NTOK, INTER, HID);
    // 12. g = silu(g) * u (rounded)
    silu_mul<<<4096, blk>>>(gg, uu, (size_t)NTOK * INTER);
    // 13. out = x1 + g @ Wd^T  K=10944
    tf32gemm<1><<<dim3(16, 32), 128, GEMM_SMEM>>>(gg, Wd, x1, out, NTOK, HID, INTER);
}

// round 7
// speedup vs baseline: 1.3778x; 1.2088x over previous
#include <cuda_runtime.h>
#include <cuda_fp16.h>
#include <math.h>
#include <stdint.h>

// ---------------- Problem constants (fixed shapes) ----------------
#define BATCH 2
#define SEQ   2048
#define NTOK  (BATCH*SEQ)        // 4096
#define HID   2048
#define NH    16
#define DQ    192
#define DNOPE 128
#define DROPE 64
#define DV    128
#define KVR   512
#define INTER 10944

// ---------------- Scratch (device globals; allocation-free) ----------------
__device__ __half h_xln [NTOK*HID];      // GEMM A operands (fp16)
__device__ __half h_cln [NTOK*KVR];
__device__ __half h_attn[NTOK*HID];
__device__ __half h_y   [NTOK*HID];
__device__ __half h_gh  [NTOK*INTER];
__device__ float g_q   [NTOK*NH*DQ];     // fp32 intermediates
__device__ float g_ckv [NTOK*(KVR+DROPE)];
__device__ float g_kv  [NTOK*NH*(DNOPE+DV)];
__device__ float g_qf  [BATCH*NH*SEQ*DQ];
__device__ float g_kf  [BATCH*NH*SEQ*DQ];
__device__ float g_v   [BATCH*NH*SEQ*DV];
__device__ float g_x1  [NTOK*HID];
__device__ float g_g   [NTOK*INTER];
__device__ float g_u   [NTOK*INTER];

// ---------------- RMSNorm (fp32 in, fp16 out: feeds GEMMs only) ----------
__global__ void rmsnorm_kernel(const float* __restrict__ in, const float* __restrict__ w,
                               __half* __restrict__ out, int cols, int instride) {
    int row = blockIdx.x;
    int tid = threadIdx.x;
    const float* xr = in + (size_t)row * instride;
    float s = 0.f;
    for (int c = tid; c < cols; c += 256) { float v = xr[c]; s += v * v; }
    __shared__ float red[8];
    for (int o = 16; o; o >>= 1) s += __shfl_xor_sync(0xffffffffu, s, o);
    if ((tid & 31) == 0) red[tid >> 5] = s;
    __syncthreads();
    float tot = 0.f;
    #pragma unroll
    for (int i = 0; i < 8; i++) tot += red[i];
    float inv = rsqrtf(tot / (float)cols + 1e-6f);
    for (int c = tid; c < cols; c += 256)
        out[(size_t)row * cols + c] = __float2half_rn(xr[c] * inv * w[c]);
}

// ---------------- FP16 mma.sync GEMM (fp32 accumulate) --------------------
// C[M,N] = A[M,K] @ W[N,K]^T (+R). A is __half (producer-converted);
// W is raw fp32, converted (rn) during smem store.
// CTA 128x128, BK=32, 128 threads = 4 warps (2m x 2n), warp tile 64x64.
// A: 2-stage cp.async. W: LDG float4 prefetch -> cvt -> STS.
// Requirements: M % 128 == 0, K % 32 == 0, N arbitrary (guarded).
#define HPITCH 40                          // halves per smem row (80 B)
#define HSTG  (128*HPITCH)                 // halves per stage per matrix
#define GEMM_SMEM (4*HSTG*2)               // bytes: 2 stages x (A + W)
template<int EPI>   // 0: none, 1: add residual R[M,N]
__global__ void __launch_bounds__(128, 2)
h16gemm(const __half* __restrict__ A, const float* __restrict__ W,
        const float* __restrict__ R, float* __restrict__ C,
        int M, int N, int K) {
    extern __shared__ __half smh[];
    __half* AsB = smh;                     // 2 stages
    __half* WsB = smh + 2 * HSTG;

    const int tid  = threadIdx.x;
    const int warp = tid >> 5, lane = tid & 31;
    const int wm = warp >> 1;              // 0..1 -> 64 rows
    const int wn = warp & 1;               // 0..1 -> 64 cols
    const int g = lane >> 2, t = lane & 3;
    const int bm = blockIdx.y * 128;
    const int bn = blockIdx.x * 128;

    float acc[4][8][4];
    #pragma unroll
    for (int i = 0; i < 4; i++)
        #pragma unroll
        for (int j = 0; j < 8; j++)
            #pragma unroll
            for (int c = 0; c < 4; c++) acc[i][j][c] = 0.f;

    // ---- A loader: 4 x 16B cp.async per thread (128x32 halves) ----
    auto load_A = [&](int s, int k0) {
        #pragma unroll
        for (int i = 0; i < 4; i++) {
            int ch = tid + 128 * i;        // 0..511
            int m = ch >> 2, c8 = (ch & 3) * 8;
            uint32_t d = (uint32_t)__cvta_generic_to_shared(&AsB[s * HSTG + m * HPITCH + c8]);
            const __half* src = &A[(size_t)(bm + m) * K + k0 + c8];
            asm volatile("cp.async.cg.shared.global [%0], [%1], 16;" :: "r"(d), "l"(src));
        }
        asm volatile("cp.async.commit_group;" ::: "memory");
    };
    // ---- W loader: LDG float4 into regs ----
    auto ldg_W = [&](int k0, float4* wreg) {
        #pragma unroll
        for (int i = 0; i < 8; i++) {
            int ch = tid + 128 * i;
            int n = bn + (ch >> 3), c4 = (ch & 7) * 4;
            const float* src = &W[(size_t)(n < N ? n : 0) * K + k0 + c4];
            wreg[i] = *(const float4*)src;
        }
    };
    auto sts_W = [&](int s, const float4* wreg) {
        #pragma unroll
        for (int i = 0; i < 8; i++) {
            int ch = tid + 128 * i;
            int n = ch >> 3, c4 = (ch & 7) * 4;
            __half2 h0 = __floats2half2_rn(wreg[i].x, wreg[i].y);
            __half2 h1 = __floats2half2_rn(wreg[i].z, wreg[i].w);
            uint2 pk = make_uint2(*(uint32_t*)&h0, *(uint32_t*)&h1);
            *(uint2*)&WsB[s * HSTG + n * HPITCH + c4] = pk;
        }
    };

    auto compute = [&](int s) {
        const __half* Ab = &AsB[s * HSTG];
        const __half* Wb = &WsB[s * HSTG];
        #pragma unroll
        for (int ks = 0; ks < 2; ks++) {   // two k16 steps per BK=32
            int kk = ks * 16;
            uint32_t af[4][4];
            #pragma unroll
            for (int i = 0; i < 4; i++) {
                int r = wm * 64 + i * 16 + g;
                af[i][0] = *(const uint32_t*)&Ab[(r    ) * HPITCH + kk + 2 * t    ];
                af[i][1] = *(const uint32_t*)&Ab[(r + 8) * HPITCH + kk + 2 * t    ];
                af[i][2] = *(const uint32_t*)&Ab[(r    ) * HPITCH + kk + 2 * t + 8];
                af[i][3] = *(const uint32_t*)&Ab[(r + 8) * HPITCH + kk + 2 * t + 8];
            }
            uint32_t bf[8][2];
            #pragma unroll
            for (int j = 0; j < 8; j++) {
                int n = wn * 64 + j * 8 + g;
                bf[j][0] = *(const uint32_t*)&Wb[n * HPITCH + kk + 2 * t    ];
                bf[j][1] = *(const uint32_t*)&Wb[n * HPITCH + kk + 2 * t + 8];
            }
            #pragma unroll
            for (int i = 0; i < 4; i++)
                #pragma unroll
                for (int j = 0; j < 8; j++) {
                    asm volatile(
                        "mma.sync.aligned.m16n8k16.row.col.f32.f16.f16.f32 "
                        "{%0,%1,%2,%3}, {%4,%5,%6,%7}, {%8,%9}, {%0,%1,%2,%3};"
                        : "+f"(acc[i][j][0]), "+f"(acc[i][j][1]),
                          "+f"(acc[i][j][2]), "+f"(acc[i][j][3])
                        : "r"(af[i][0]), "r"(af[i][1]), "r"(af[i][2]), "r"(af[i][3]),
                          "r"(bf[j][0]), "r"(bf[j][1]));
                }
        }
    };

    // ---- prologue ----
    float4 wreg[8];
    load_A(0, 0);
    ldg_W(0, wreg);
    asm volatile("cp.async.wait_group 0;" ::: "memory");
    __syncthreads();
    sts_W(0, wreg);
    __syncthreads();

    const int NK = K >> 5;
    for (int i = 0; i < NK; i++) {
        int s = i & 1;
        if (i + 1 < NK) {
            load_A(s ^ 1, (i + 1) * 32);
            ldg_W((i + 1) * 32, wreg);
        }
        compute(s);
        if (i + 1 < NK) {
            asm volatile("cp.async.wait_group 0;" ::: "memory");
            __syncthreads();
            sts_W(s ^ 1, wreg);
            __syncthreads();
        }
    }

    // ---- epilogue ----
    #pragma unroll
    for (int i = 0; i < 4; i++) {
        int r0 = bm + wm * 64 + i * 16 + g;
        #pragma unroll
        for (int j = 0; j < 8; j++) {
            int c = bn + wn * 64 + j * 8 + 2 * t;
            if (c < N) {
                float2 v0 = make_float2(acc[i][j][0], acc[i][j][1]);
                float2 v1 = make_float2(acc[i][j][2], acc[i][j][3]);
                if (EPI == 1) {
                    float2 r = *(const float2*)&R[(size_t)r0 * N + c];
                    v0.x += r.x; v0.y += r.y;
                    float2 r2 = *(const float2*)&R[(size_t)(r0 + 8) * N + c];
                    v1.x += r2.x; v1.y += r2.y;
                }
                *(float2*)&C[(size_t)r0 * N + c]       = v0;
                *(float2*)&C[(size_t)(r0 + 8) * N + c] = v1;
            }
        }
    }
}

// ---------------- RoPE (yarn) helpers ----------------
__device__ __forceinline__ void yarn_cossin(int j, int pos, float& c, float& s) {
    float ar = (float)j * (1.0f / 32.0f);
    float fe = __powf(10000.0f, -ar);
    float fi = fe * (1.0f / 40.0f);
    float ramp = fminf(fmaxf(((float)j - 10.0f) * (1.0f / 13.0f), 0.0f), 1.0f);
    float f = fi * ramp + fe * (1.0f - ramp);
    float a = (float)pos * f;
    c = cosf(a); s = sinf(a);
}

// q [NTOK, NH*DQ] -> qf [B,H,S,DQ] with rope on last 64 (deinterleaved)
__global__ void build_qf(const float* __restrict__ q, const int* __restrict__ pos_ids,
                         float* __restrict__ qf) {
    int t = blockIdx.x;
    int b = t / SEQ, s = t % SEQ;
    int tid = threadIdx.x;              // 128
    __shared__ float cs[32], sn[32];
    int pos = pos_ids[t];
    if (tid < 32) yarn_cossin(tid, pos, cs[tid], sn[tid]);
    __syncthreads();
    for (int h = 0; h < NH; h++) {
        size_t src = (size_t)t * (NH * DQ) + h * DQ;
        size_t dst = ((size_t)(b * NH + h) * SEQ + s) * DQ;
        qf[dst + tid] = q[src + tid];
        if (tid < 32) {
            float p0 = q[src + DNOPE + 2 * tid];
            float p1 = q[src + DNOPE + 2 * tid + 1];
            qf[dst + DNOPE + tid]      = p0 * cs[tid] - p1 * sn[tid];
            qf[dst + DNOPE + 32 + tid] = p1 * cs[tid] + p0 * sn[tid];
        }
    }
}

// kv [NTOK, NH*256], ckv [NTOK, 576] -> kf [B,H,S,192], v [B,H,S,128]
__global__ void build_kf(const float* __restrict__ kv, const float* __restrict__ ckv,
                         const int* __restrict__ pos_ids,
                         float* __restrict__ kf, float* __restrict__ vv) {
    int t = blockIdx.x;
    int b = t / SEQ, s = t % SEQ;
    int tid = threadIdx.x;              // 128
    __shared__ float cs[32], sn[32], kr[64];
    int pos = pos_ids[t];
    if (tid < 32) yarn_cossin(tid, pos, cs[tid], sn[tid]);
    __syncthreads();
    if (tid < 32) {
        float p0 = ckv[(size_t)t * (KVR + DROPE) + KVR + 2 * tid];
        float p1 = ckv[(size_t)t * (KVR + DROPE) + KVR + 2 * tid + 1];
        kr[tid]      = p0 * cs[tid] - p1 * sn[tid];
        kr[tid + 32] = p1 * cs[tid] + p0 * sn[tid];
    }
    __syncthreads();
    for (int h = 0; h < NH; h++) {
        size_t src = (size_t)t * (NH * 256) + h * 256;
        size_t d0 = ((size_t)(b * NH + h) * SEQ + s);
        kf[d0 * DQ + tid] = kv[src + tid];
        vv[d0 * DV + tid] = kv[src + DNOPE + tid];
        if (tid < 64) kf[d0 * DQ + DNOPE + tid] = kr[tid];
    }
}

// ---------------- Causal attention, online softmax (fp16 out) -------------
__global__ void __launch_bounds__(256)
attn_kernel(const float* __restrict__ qf, const float* __restrict__ kf,
            const float* __restrict__ vv, __half* __restrict__ out) {
    __shared__ float qs[16][196];
    __shared__ float ks[16][196];
    __shared__ float vs[16][128];
    __shared__ float lg[16][16];
    int tid = threadIdx.x;
    int q16 = tid >> 4, x16 = tid & 15;
    int b = blockIdx.z, h = blockIdx.y;
    int q0 = blockIdx.x * 16;
    size_t bqk = (size_t)(b * NH + h) * SEQ * DQ;
    size_t bv  = (size_t)(b * NH + h) * SEQ * DV;

    for (int i = tid; i < 16 * 48; i += 256) {
        int r = i / 48, c4 = i % 48;
        *(float4*)&qs[r][c4 * 4] = *(const float4*)&qf[bqk + (size_t)(q0 + r) * DQ + c4 * 4];
    }
    float acc[8];
    #pragma unroll
    for (int j = 0; j < 8; j++) acc[j] = 0.f;
    float m = -INFINITY, l = 0.f;
    int myq = q0 + q16;
    const float scale = 0.07216878364870323f;    // 192^-0.5

    for (int kc = 0; kc < q0 + 16; kc += 16) {
        __syncthreads();
        for (int i = tid; i < 16 * 48; i += 256) {
            int r = i / 48, c4 = i % 48;
            *(float4*)&ks[r][c4 * 4] = *(const float4*)&kf[bqk + (size_t)(kc + r) * DQ + c4 * 4];
        }
        for (int i = tid; i < 16 * 32; i += 256) {
            int r = i / 32, c4 = i % 32;
            *(float4*)&vs[r][c4 * 4] = *(const float4*)&vv[bv + (size_t)(kc + r) * DV + c4 * 4];
        }
        __syncthreads();
        float dot = 0.f;
        #pragma unroll 8
        for (int d = 0; d < DQ; d += 4) {
            float4 a = *(const float4*)&qs[q16][d];
            float4 k4 = *(const float4*)&ks[x16][d];
            dot += a.x * k4.x + a.y * k4.y + a.z * k4.z + a.w * k4.w;
        }
        lg[q16][x16] = (kc + x16 <= myq) ? dot * scale : -INFINITY;
        __syncthreads();
        float cmax = -INFINITY;
        #pragma unroll
        for (int k = 0; k < 16; k++) cmax = fmaxf(cmax, lg[q16][k]);
        float nm = fmaxf(m, cmax);
        float corr = __expf(m - nm);
        l *= corr;
        #pragma unroll
        for (int j = 0; j < 8; j++) acc[j] *= corr;
        #pragma unroll
        for (int k = 0; k < 16; k++) {
            float p = __expf(lg[q16][k] - nm);
            l += p;
            const float* vr = &vs[k][x16 * 8];
            #pragma unroll
            for (int j = 0; j < 8; j++) acc[j] += p * vr[j];
        }
        m = nm;
    }
    float inv = 1.0f / l;
    size_t o = ((size_t)(b * SEQ + myq)) * (NH * DV) + h * DV + x16 * 8;
    #pragma unroll
    for (int j = 0; j < 8; j++) out[o + j] = __float2half_rn(acc[j] * inv);
}

// ---------------- SiLU(g)*u -> fp16 (feeds Wd GEMM) ----------------------
__global__ void silu_mul(const float* __restrict__ g, const float* __restrict__ u,
                         __half* __restrict__ o, size_t n) {
    for (size_t i = (size_t)blockIdx.x * blockDim.x + threadIdx.x; i < n;
         i += (size_t)gridDim.x * blockDim.x) {
        float x = g[i];
        o[i] = __float2half_rn(x / (1.0f + __expf(-x)) * u[i]);
    }
}

// ---------------- Launch ----------------
extern "C" void kernel_launch(void* const* d_in, const int* in_sizes, int n_in,
                              void* d_out, int out_size) {
    const float* hidden = (const float*)d_in[0];
    const int*   pos    = (const int*)d_in[1];
    const float* Wq     = (const float*)d_in[2];
    const float* Wkva   = (const float*)d_in[3];
    const float* w_kvln = (const float*)d_in[4];
    const float* Wkvb   = (const float*)d_in[5];
    const float* Wo     = (const float*)d_in[6];
    const float* Wg     = (const float*)d_in[7];
    const float* Wu     = (const float*)d_in[8];
    const float* Wd     = (const float*)d_in[9];
    const float* w_ln1  = (const float*)d_in[10];
    const float* w_ln2  = (const float*)d_in[11];
    float* out = (float*)d_out;

    __half *xln, *cln, *attn, *yh, *gh;
    float *q, *ckv, *kv, *qfp, *kfp, *vp, *x1, *gg, *uu;
    cudaGetSymbolAddress((void**)&xln,  h_xln);
    cudaGetSymbolAddress((void**)&cln,  h_cln);
    cudaGetSymbolAddress((void**)&attn, h_attn);
    cudaGetSymbolAddress((void**)&yh,   h_y);
    cudaGetSymbolAddress((void**)&gh,   h_gh);
    cudaGetSymbolAddress((void**)&q,    g_q);
    cudaGetSymbolAddress((void**)&ckv,  g_ckv);
    cudaGetSymbolAddress((void**)&kv,   g_kv);
    cudaGetSymbolAddress((void**)&qfp,  g_qf);
    cudaGetSymbolAddress((void**)&kfp,  g_kf);
    cudaGetSymbolAddress((void**)&vp,   g_v);
    cudaGetSymbolAddress((void**)&x1,   g_x1);
    cudaGetSymbolAddress((void**)&gg,   g_g);
    cudaGetSymbolAddress((void**)&uu,   g_u);

    cudaFuncSetAttribute(h16gemm<0>, cudaFuncAttributeMaxDynamicSharedMemorySize, GEMM_SMEM);
    cudaFuncSetAttribute(h16gemm<1>, cudaFuncAttributeMaxDynamicSharedMemorySize, GEMM_SMEM);

    dim3 blk(256);
    // 1. ln1 (fp16 out)
    rmsnorm_kernel<<<NTOK, blk>>>(hidden, w_ln1, xln, HID, HID);
    // 2. q = xln @ Wq^T   [4096 x 3072] K=2048
    h16gemm<0><<<dim3(24, 32), 128, GEMM_SMEM>>>(xln, Wq, nullptr, q, NTOK, NH * DQ, HID);
    // 3. ckv = xln @ Wkva^T  [4096 x 576] K=2048
    h16gemm<0><<<dim3(5, 32), 128, GEMM_SMEM>>>(xln, Wkva, nullptr, ckv, NTOK, KVR + DROPE, HID);
    // 4. c_ln = rms(ckv[:, :512]) * w_kvln (fp16 out)
    rmsnorm_kernel<<<NTOK, blk>>>(ckv, w_kvln, cln, KVR, KVR + DROPE);
    // 5. kv = c_ln @ Wkvb^T  [4096 x 4096] K=512
    h16gemm<0><<<dim3(32, 32), 128, GEMM_SMEM>>>(cln, Wkvb, nullptr, kv, NTOK, NH * 256, KVR);
    // 6/7. layouts + rope
    build_qf<<<NTOK, 128>>>(q, pos, qfp);
    build_kf<<<NTOK, 128>>>(kv, ckv, pos, kfp, vp);
    // 8. attention (fp16 out)
    attn_kernel<<<dim3(SEQ / 16, NH, BATCH), blk>>>(qfp, kfp, vp, attn);
    // 9. x1 = hidden + attn @ Wo^T  K=2048
    h16gemm<1><<<dim3(16, 32), 128, GEMM_SMEM>>>(attn, Wo, hidden, x1, NTOK, HID, NH * DV);
    // 10. y = rms(x1) * w_ln2 (fp16 out)
    rmsnorm_kernel<<<NTOK, blk>>>(x1, w_ln2, yh, HID, HID);
    // 11. g = y @ Wg^T, u = y @ Wu^T  [4096 x 10944] K=2048
    h16gemm<0><<<dim3(86, 32), 128, GEMM_SMEM>>>(yh, Wg, nullptr, gg, NTOK, INTER, HID);
    h16gemm<0><<<dim3(86, 32), 128, GEMM_SMEM>>>(yh, Wu, nullptr, uu, NTOK, INTER, HID);
    // 12. gh = silu(g) * u (fp16 out)
    silu_mul<<<4096, blk>>>(gg, uu, gh, (size_t)NTOK * INTER);
    // 13. out = x1 + gh @ Wd^T  K=10944
    h16gemm<1><<<dim3(16, 32), 128, GEMM_SMEM>>>(gh, Wd, x1, out, NTOK, HID, INTER);
}

// round 8
// speedup vs baseline: 1.4702x; 1.0671x over previous
#include <cuda_runtime.h>
#include <cuda_fp16.h>
#include <math.h>
#include <stdint.h>

// ---------------- Problem constants (fixed shapes) ----------------
#define BATCH 2
#define SEQ   2048
#define NTOK  (BATCH*SEQ)        // 4096
#define HID   2048
#define NH    16
#define DQ    192
#define DNOPE 128
#define DROPE 64
#define DV    128
#define KVR   512
#define INTER 10944

// ---------------- Scratch (device globals; allocation-free) ----------------
__device__ __half h_xln [NTOK*HID];      // GEMM A operands (fp16)
__device__ __half h_cln [NTOK*KVR];
__device__ __half h_attn[NTOK*HID];
__device__ __half h_y   [NTOK*HID];
__device__ __half h_gh  [NTOK*INTER];
__device__ float g_q   [NTOK*NH*DQ];     // fp32 intermediates
__device__ float g_ckv [NTOK*(KVR+DROPE)];
__device__ float g_kv  [NTOK*NH*(DNOPE+DV)];
__device__ float g_qf  [BATCH*NH*SEQ*DQ];
__device__ float g_kf  [BATCH*NH*SEQ*DQ];
__device__ float g_v   [BATCH*NH*SEQ*DV];
__device__ float g_x1  [NTOK*HID];
__device__ float g_g   [NTOK*INTER];
__device__ float g_u   [NTOK*INTER];
// fp16 weight copies
__device__ __half hw_q  [NH*DQ*HID];
__device__ __half hw_kva[(KVR+DROPE)*HID];
__device__ __half hw_kvb[NH*(DNOPE+DV)*KVR];
__device__ __half hw_o  [HID*NH*DV];
__device__ __half hw_g  [INTER*HID];
__device__ __half hw_u  [INTER*HID];
__device__ __half hw_d  [HID*INTER];

// ---------------- weight fp32 -> fp16 ----------------
__global__ void w2h_kernel(const float* __restrict__ in, __half* __restrict__ out, int n4) {
    int i = blockIdx.x * blockDim.x + threadIdx.x;
    if (i < n4) {
        float4 v = ((const float4*)in)[i];
        __half2 h0 = __floats2half2_rn(v.x, v.y);
        __half2 h1 = __floats2half2_rn(v.z, v.w);
        ((uint2*)out)[i] = make_uint2(*(uint32_t*)&h0, *(uint32_t*)&h1);
    }
}

// ---------------- RMSNorm (fp32 in, fp16 out: feeds GEMMs only) ----------
__global__ void rmsnorm_kernel(const float* __restrict__ in, const float* __restrict__ w,
                               __half* __restrict__ out, int cols, int instride) {
    int row = blockIdx.x;
    int tid = threadIdx.x;
    const float* xr = in + (size_t)row * instride;
    float s = 0.f;
    for (int c = tid; c < cols; c += 256) { float v = xr[c]; s += v * v; }
    __shared__ float red[8];
    for (int o = 16; o; o >>= 1) s += __shfl_xor_sync(0xffffffffu, s, o);
    if ((tid & 31) == 0) red[tid >> 5] = s;
    __syncthreads();
    float tot = 0.f;
    #pragma unroll
    for (int i = 0; i < 8; i++) tot += red[i];
    float inv = rsqrtf(tot / (float)cols + 1e-6f);
    for (int c = tid; c < cols; c += 256)
        out[(size_t)row * cols + c] = __float2half_rn(xr[c] * inv * w[c]);
}

// ---------------- FP16 mma.sync GEMM (fp32 acc), 3-stage, ldmatrix --------
// C[M,N] = A[M,K] @ W[N,K]^T (+R). A, W both fp16 K-major in global.
// CTA 128x128, BK=32, 128 threads = 4 warps (2m x 2n), warp 64x64.
// 3-stage cp.async, single __syncthreads per iter, ldmatrix.x4 fragments.
// Requirements: M % 128 == 0, K % 32 == 0 (and K/32 >= 2), N guarded.
#define HPITCH 40                          // halves per smem row (80 B)
#define HSTG  (128*HPITCH)                 // halves per matrix per stage
#define GEMM_SMEM (3*2*HSTG*2)             // bytes: 3 stages x (A+W)
__device__ __forceinline__ void ldsm4(uint32_t& r0, uint32_t& r1, uint32_t& r2, uint32_t& r3,
                                      uint32_t addr) {
    asm volatile("ldmatrix.sync.aligned.m8n8.x4.shared.b16 {%0,%1,%2,%3}, [%4];"
                 : "=r"(r0), "=r"(r1), "=r"(r2), "=r"(r3) : "r"(addr));
}
template<int EPI>   // 0: none, 1: add residual R[M,N]
__global__ void __launch_bounds__(128, 2)
h16gemm(const __half* __restrict__ A, const __half* __restrict__ W,
        const float* __restrict__ R, float* __restrict__ C,
        int M, int N, int K) {
    extern __shared__ __half smh[];
    const uint32_t sbase = (uint32_t)__cvta_generic_to_shared(smh);

    const int tid  = threadIdx.x;
    const int warp = tid >> 5, lane = tid & 31;
    const int wm = warp >> 1;              // 0..1 -> 64 rows
    const int wn = warp & 1;               // 0..1 -> 64 cols
    const int g = lane >> 2, t = lane & 3;
    const int bm = blockIdx.y * 128;
    const int bn = blockIdx.x * 128;

    float acc[4][8][4];
    #pragma unroll
    for (int i = 0; i < 4; i++)
        #pragma unroll
        for (int j = 0; j < 8; j++)
            #pragma unroll
            for (int c = 0; c < 4; c++) acc[i][j][c] = 0.f;

    // per-lane ldmatrix address components
    const int arow = wm * 64 + (lane & 15);
    const int acol = (lane >> 4) << 3;
    const int brow = wn * 64 + ((lane >> 4) << 3) + (lane & 7);
    const int bcol = ((lane >> 3) & 1) << 3;

    // ---- stage loader: A + W, 4 cp.async each per thread, one commit ----
    auto load_stage = [&](int s, int k0) {
        uint32_t sA = sbase + (uint32_t)(s * 2 * HSTG) * 2;
        uint32_t sW = sA + (uint32_t)HSTG * 2;
        #pragma unroll
        for (int i = 0; i < 4; i++) {
            int ch = tid + 128 * i;        // 0..511
            int m = ch >> 2, c8 = (ch & 3) * 8;
            uint32_t d = sA + (uint32_t)(m * HPITCH + c8) * 2;
            const __half* src = &A[(size_t)(bm + m) * K + k0 + c8];
            asm volatile("cp.async.cg.shared.global [%0], [%1], 16;" :: "r"(d), "l"(src));
            int n = bn + m;
            int ok = (n < N) ? 16 : 0;
            uint32_t dw = sW + (uint32_t)(m * HPITCH + c8) * 2;
            const __half* srcw = &W[(size_t)(n < N ? n : 0) * K + k0 + c8];
            asm volatile("cp.async.cg.shared.global [%0], [%1], 16, %2;"
                         :: "r"(dw), "l"(srcw), "r"(ok));
        }
        asm volatile("cp.async.commit_group;" ::: "memory");
    };

    auto compute = [&](int s) {
        uint32_t sA = sbase + (uint32_t)(s * 2 * HSTG) * 2;
        uint32_t sW = sA + (uint32_t)HSTG * 2;
        #pragma unroll
        for (int ks = 0; ks < 2; ks++) {
            int kk = ks * 16;
            uint32_t af[4][4];
            #pragma unroll
            for (int i = 0; i < 4; i++)
                ldsm4(af[i][0], af[i][1], af[i][2], af[i][3],
                      sA + (uint32_t)((arow + i * 16) * HPITCH + kk + acol) * 2);
            uint32_t bf[8][2];
            #pragma unroll
            for (int jj = 0; jj < 4; jj++)
                ldsm4(bf[2 * jj][0], bf[2 * jj][1], bf[2 * jj + 1][0], bf[2 * jj + 1][1],
                      sW + (uint32_t)((brow + jj * 16) * HPITCH + kk + bcol) * 2);
            #pragma unroll
            for (int i = 0; i < 4; i++)
                #pragma unroll
                for (int j = 0; j < 8; j++) {
                    asm volatile(
                        "mma.sync.aligned.m16n8k16.row.col.f32.f16.f16.f32 "
                        "{%0,%1,%2,%3}, {%4,%5,%6,%7}, {%8,%9}, {%0,%1,%2,%3};"
                        : "+f"(acc[i][j][0]), "+f"(acc[i][j][1]),
                          "+f"(acc[i][j][2]), "+f"(acc[i][j][3])
                        : "r"(af[i][0]), "r"(af[i][1]), "r"(af[i][2]), "r"(af[i][3]),
                          "r"(bf[j][0]), "r"(bf[j][1]));
                }
        }
    };

    const int NK = K >> 5;
    load_stage(0, 0);
    load_stage(1, 32);

    for (int i = 0; i < NK; i++) {
        if (i + 1 < NK) asm volatile("cp.async.wait_group 1;" ::: "memory");
        else            asm volatile("cp.async.wait_group 0;" ::: "memory");
        __syncthreads();                       // loads(i) visible; compute(i-1) done
        if (i + 2 < NK) load_stage((i + 2) % 3, (i + 2) * 32);
        compute(i % 3);
    }

    // ---- epilogue ----
    #pragma unroll
    for (int i = 0; i < 4; i++) {
        int r0 = bm + wm * 64 + i * 16 + g;
        #pragma unroll
        for (int j = 0; j < 8; j++) {
            int c = bn + wn * 64 + j * 8 + 2 * t;
            if (c < N) {
                float2 v0 = make_float2(acc[i][j][0], acc[i][j][1]);
                float2 v1 = make_float2(acc[i][j][2], acc[i][j][3]);
                if (EPI == 1) {
                    float2 r = *(const float2*)&R[(size_t)r0 * N + c];
                    v0.x += r.x; v0.y += r.y;
                    float2 r2 = *(const float2*)&R[(size_t)(r0 + 8) * N + c];
                    v1.x += r2.x; v1.y += r2.y;
                }
                *(float2*)&C[(size_t)r0 * N + c]       = v0;
                *(float2*)&C[(size_t)(r0 + 8) * N + c] = v1;
            }
        }
    }
}

// ---------------- RoPE (yarn) helpers ----------------
__device__ __forceinline__ void yarn_cossin(int j, int pos, float& c, float& s) {
    float ar = (float)j * (1.0f / 32.0f);
    float fe = __powf(10000.0f, -ar);
    float fi = fe * (1.0f / 40.0f);
    float ramp = fminf(fmaxf(((float)j - 10.0f) * (1.0f / 13.0f), 0.0f), 1.0f);
    float f = fi * ramp + fe * (1.0f - ramp);
    float a = (float)pos * f;
    c = cosf(a); s = sinf(a);
}

// q [NTOK, NH*DQ] -> qf [B,H,S,DQ] with rope on last 64 (deinterleaved)
__global__ void build_qf(const float* __restrict__ q, const int* __restrict__ pos_ids,
                         float* __restrict__ qf) {
    int t = blockIdx.x;
    int b = t / SEQ, s = t % SEQ;
    int tid = threadIdx.x;              // 128
    __shared__ float cs[32], sn[32];
    int pos = pos_ids[t];
    if (tid < 32) yarn_cossin(tid, pos, cs[tid], sn[tid]);
    __syncthreads();
    for (int h = 0; h < NH; h++) {
        size_t src = (size_t)t * (NH * DQ) + h * DQ;
        size_t dst = ((size_t)(b * NH + h) * SEQ + s) * DQ;
        qf[dst + tid] = q[src + tid];
        if (tid < 32) {
            float p0 = q[src + DNOPE + 2 * tid];
            float p1 = q[src + DNOPE + 2 * tid + 1];
            qf[dst + DNOPE + tid]      = p0 * cs[tid] - p1 * sn[tid];
            qf[dst + DNOPE + 32 + tid] = p1 * cs[tid] + p0 * sn[tid];
        }
    }
}

// kv [NTOK, NH*256], ckv [NTOK, 576] -> kf [B,H,S,192], v [B,H,S,128]
__global__ void build_kf(const float* __restrict__ kv, const float* __restrict__ ckv,
                         const int* __restrict__ pos_ids,
                         float* __restrict__ kf, float* __restrict__ vv) {
    int t = blockIdx.x;
    int b = t / SEQ, s = t % SEQ;
    int tid = threadIdx.x;              // 128
    __shared__ float cs[32], sn[32], kr[64];
    int pos = pos_ids[t];
    if (tid < 32) yarn_cossin(tid, pos, cs[tid], sn[tid]);
    __syncthreads();
    if (tid < 32) {
        float p0 = ckv[(size_t)t * (KVR + DROPE) + KVR + 2 * tid];
        float p1 = ckv[(size_t)t * (KVR + DROPE) + KVR + 2 * tid + 1];
        kr[tid]      = p0 * cs[tid] - p1 * sn[tid];
        kr[tid + 32] = p1 * cs[tid] + p0 * sn[tid];
    }
    __syncthreads();
    for (int h = 0; h < NH; h++) {
        size_t src = (size_t)t * (NH * 256) + h * 256;
        size_t d0 = ((size_t)(b * NH + h) * SEQ + s);
        kf[d0 * DQ + tid] = kv[src + tid];
        vv[d0 * DV + tid] = kv[src + DNOPE + tid];
        if (tid < 64) kf[d0 * DQ + DNOPE + tid] = kr[tid];
    }
}

// ---------------- Causal attention, online softmax (fp16 out) -------------
__global__ void __launch_bounds__(256)
attn_kernel(const float* __restrict__ qf, const float* __restrict__ kf,
            const float* __restrict__ vv, __half* __restrict__ out) {
    __shared__ float qs[16][196];
    __shared__ float ks[16][196];
    __shared__ float vs[16][128];
    __shared__ float lg[16][16];
    int tid = threadIdx.x;
    int q16 = tid >> 4, x16 = tid & 15;
    int b = blockIdx.z, h = blockIdx.y;
    int q0 = blockIdx.x * 16;
    size_t bqk = (size_t)(b * NH + h) * SEQ * DQ;
    size_t bv  = (size_t)(b * NH + h) * SEQ * DV;

    for (int i = tid; i < 16 * 48; i += 256) {
        int r = i / 48, c4 = i % 48;
        *(float4*)&qs[r][c4 * 4] = *(const float4*)&qf[bqk + (size_t)(q0 + r) * DQ + c4 * 4];
    }
    float acc[8];
    #pragma unroll
    for (int j = 0; j < 8; j++) acc[j] = 0.f;
    float m = -INFINITY, l = 0.f;
    int myq = q0 + q16;
    const float scale = 0.07216878364870323f;    // 192^-0.5

    for (int kc = 0; kc < q0 + 16; kc += 16) {
        __syncthreads();
        for (int i = tid; i < 16 * 48; i += 256) {
            int r = i / 48, c4 = i % 48;
            *(float4*)&ks[r][c4 * 4] = *(const float4*)&kf[bqk + (size_t)(kc + r) * DQ + c4 * 4];
        }
        for (int i = tid; i < 16 * 32; i += 256) {
            int r = i / 32, c4 = i % 32;
            *(float4*)&vs[r][c4 * 4] = *(const float4*)&vv[bv + (size_t)(kc + r) * DV + c4 * 4];
        }
        __syncthreads();
        float dot = 0.f;
        #pragma unroll 8
        for (int d = 0; d < DQ; d += 4) {
            float4 a = *(const float4*)&qs[q16][d];
            float4 k4 = *(const float4*)&ks[x16][d];
            dot += a.x * k4.x + a.y * k4.y + a.z * k4.z + a.w * k4.w;
        }
        lg[q16][x16] = (kc + x16 <= myq) ? dot * scale : -INFINITY;
        __syncthreads();
        float cmax = -INFINITY;
        #pragma unroll
        for (int k = 0; k < 16; k++) cmax = fmaxf(cmax, lg[q16][k]);
        float nm = fmaxf(m, cmax);
        float corr = __expf(m - nm);
        l *= corr;
        #pragma unroll
        for (int j = 0; j < 8; j++) acc[j] *= corr;
        #pragma unroll
        for (int k = 0; k < 16; k++) {
            float p = __expf(lg[q16][k] - nm);
            l += p;
            const float* vr = &vs[k][x16 * 8];
            #pragma unroll
            for (int j = 0; j < 8; j++) acc[j] += p * vr[j];
        }
        m = nm;
    }
    float inv = 1.0f / l;
    size_t o = ((size_t)(b * SEQ + myq)) * (NH * DV) + h * DV + x16 * 8;
    #pragma unroll
    for (int j = 0; j < 8; j++) out[o + j] = __float2half_rn(acc[j] * inv);
}

// ---------------- SiLU(g)*u -> fp16 (feeds Wd GEMM) ----------------------
__global__ void silu_mul(const float* __restrict__ g, const float* __restrict__ u,
                         __half* __restrict__ o, size_t n) {
    for (size_t i = (size_t)blockIdx.x * blockDim.x + threadIdx.x; i < n;
         i += (size_t)gridDim.x * blockDim.x) {
        float x = g[i];
        o[i] = __float2half_rn(x / (1.0f + __expf(-x)) * u[i]);
    }
}

// ---------------- Launch ----------------
extern "C" void kernel_launch(void* const* d_in, const int* in_sizes, int n_in,
                              void* d_out, int out_size) {
    const float* hidden = (const float*)d_in[0];
    const int*   pos    = (const int*)d_in[1];
    const float* Wq     = (const float*)d_in[2];
    const float* Wkva   = (const float*)d_in[3];
    const float* w_kvln = (const float*)d_in[4];
    const float* Wkvb   = (const float*)d_in[5];
    const float* Wo     = (const float*)d_in[6];
    const float* Wg     = (const float*)d_in[7];
    const float* Wu     = (const float*)d_in[8];
    const float* Wd     = (const float*)d_in[9];
    const float* w_ln1  = (const float*)d_in[10];
    const float* w_ln2  = (const float*)d_in[11];
    float* out = (float*)d_out;

    __half *xln, *cln, *attn, *yh, *gh;
    __half *wq, *wkva, *wkvb, *wo, *wg, *wu, *wd;
    float *q, *ckv, *kv, *qfp, *kfp, *vp, *x1, *gg, *uu;
    cudaGetSymbolAddress((void**)&xln,  h_xln);
    cudaGetSymbolAddress((void**)&cln,  h_cln);
    cudaGetSymbolAddress((void**)&attn, h_attn);
    cudaGetSymbolAddress((void**)&yh,   h_y);
    cudaGetSymbolAddress((void**)&gh,   h_gh);
    cudaGetSymbolAddress((void**)&wq,   hw_q);
    cudaGetSymbolAddress((void**)&wkva, hw_kva);
    cudaGetSymbolAddress((void**)&wkvb, hw_kvb);
    cudaGetSymbolAddress((void**)&wo,   hw_o);
    cudaGetSymbolAddress((void**)&wg,   hw_g);
    cudaGetSymbolAddress((void**)&wu,   hw_u);
    cudaGetSymbolAddress((void**)&wd,   hw_d);
    cudaGetSymbolAddress((void**)&q,    g_q);
    cudaGetSymbolAddress((void**)&ckv,  g_ckv);
    cudaGetSymbolAddress((void**)&kv,   g_kv);
    cudaGetSymbolAddress((void**)&qfp,  g_qf);
    cudaGetSymbolAddress((void**)&kfp,  g_kf);
    cudaGetSymbolAddress((void**)&vp,   g_v);
    cudaGetSymbolAddress((void**)&x1,   g_x1);
    cudaGetSymbolAddress((void**)&gg,   g_g);
    cudaGetSymbolAddress((void**)&uu,   g_u);

    cudaFuncSetAttribute(h16gemm<0>, cudaFuncAttributeMaxDynamicSharedMemorySize, GEMM_SMEM);
    cudaFuncSetAttribute(h16gemm<1>, cudaFuncAttributeMaxDynamicSharedMemorySize, GEMM_SMEM);

    dim3 blk(256);
    // 0. weights -> fp16 copies
    {
        struct { const float* s; __half* d; int n; } ws[7] = {
            {Wq,   wq,   NH*DQ*HID}, {Wkva, wkva, (KVR+DROPE)*HID},
            {Wkvb, wkvb, NH*(DNOPE+DV)*KVR}, {Wo, wo, HID*NH*DV},
            {Wg,   wg,   INTER*HID}, {Wu, wu, INTER*HID}, {Wd, wd, HID*INTER}
        };
        for (int i = 0; i < 7; i++) {
            int n4 = ws[i].n / 4;
            w2h_kernel<<<(n4 + 255) / 256, 256>>>(ws[i].s, ws[i].d, n4);
        }
    }
    // 1. ln1 (fp16 out)
    rmsnorm_kernel<<<NTOK, blk>>>(hidden, w_ln1, xln, HID, HID);
    // 2. q = xln @ Wq^T   [4096 x 3072] K=2048
    h16gemm<0><<<dim3(24, 32), 128, GEMM_SMEM>>>(xln, wq, nullptr, q, NTOK, NH * DQ, HID);
    // 3. ckv = xln @ Wkva^T  [4096 x 576] K=2048
    h16gemm<0><<<dim3(5, 32), 128, GEMM_SMEM>>>(xln, wkva, nullptr, ckv, NTOK, KVR + DROPE, HID);
    // 4. c_ln = rms(ckv[:, :512]) * w_kvln (fp16 out)
    rmsnorm_kernel<<<NTOK, blk>>>(ckv, w_kvln, cln, KVR, KVR + DROPE);
    // 5. kv = c_ln @ Wkvb^T  [4096 x 4096] K=512
    h16gemm<0><<<dim3(32, 32), 128, GEMM_SMEM>>>(cln, wkvb, nullptr, kv, NTOK, NH * 256, KVR);
    // 6/7. layouts + rope
    build_qf<<<NTOK, 128>>>(q, pos, qfp);
    build_kf<<<NTOK, 128>>>(kv, ckv, pos, kfp, vp);
    // 8. attention (fp16 out)
    attn_kernel<<<dim3(SEQ / 16, NH, BATCH), blk>>>(qfp, kfp, vp, attn);
    // 9. x1 = hidden + attn @ Wo^T  K=2048
    h16gemm<1><<<dim3(16, 32), 128, GEMM_SMEM>>>(attn, wo, hidden, x1, NTOK, HID, NH * DV);
    // 10. y = rms(x1) * w_ln2 (fp16 out)
    rmsnorm_kernel<<<NTOK, blk>>>(x1, w_ln2, yh, HID, HID);
    // 11. g = y @ Wg^T, u = y @ Wu^T  [4096 x 10944] K=2048
    h16gemm<0><<<dim3(86, 32), 128, GEMM_SMEM>>>(yh, wg, nullptr, gg, NTOK, INTER, HID);
    h16gemm<0><<<dim3(86, 32), 128, GEMM_SMEM>>>(yh, wu, nullptr, uu, NTOK, INTER, HID);
    // 12. gh = silu(g) * u (fp16 out)
    silu_mul<<<4096, blk>>>(gg, uu, gh, (size_t)NTOK * INTER);
    // 13. out = x1 + gh @ Wd^T  K=10944
    h16gemm<1><<<dim3(16, 32), 128, GEMM_SMEM>>>(gh, wd, x1, out, NTOK, HID, INTER);
}

// round 9
// speedup vs baseline: 2.8460x; 1.9358x over previous
#include <cuda_runtime.h>
#include <cuda_fp16.h>
#include <math.h>
#include <stdint.h>

// ---------------- Problem constants (fixed shapes) ----------------
#define BATCH 2
#define SEQ   2048
#define NTOK  (BATCH*SEQ)        // 4096
#define HID   2048
#define NH    16
#define DQ    192
#define DNOPE 128
#define DROPE 64
#define DV    128
#define KVR   512
#define INTER 10944

// ---------------- Scratch (device globals; allocation-free) ----------------
__device__ __half h_xln [NTOK*HID];      // GEMM A operands (fp16)
__device__ __half h_cln [NTOK*KVR];
__device__ __half h_attn[NTOK*HID];
__device__ __half h_y   [NTOK*HID];
__device__ __half h_gh  [NTOK*INTER];
__device__ __half h_qf  [BATCH*NH*SEQ*DQ];   // attention operands (fp16)
__device__ __half h_kf  [BATCH*NH*SEQ*DQ];
__device__ __half h_v   [BATCH*NH*SEQ*DV];
__device__ float g_q   [NTOK*NH*DQ];     // fp32 intermediates
__device__ float g_ckv [NTOK*(KVR+DROPE)];
__device__ float g_kv  [NTOK*NH*(DNOPE+DV)];
__device__ float g_x1  [NTOK*HID];
__device__ float g_g   [NTOK*INTER];
__device__ float g_u   [NTOK*INTER];
// fp16 weight copies
__device__ __half hw_q  [NH*DQ*HID];
__device__ __half hw_kva[(KVR+DROPE)*HID];
__device__ __half hw_kvb[NH*(DNOPE+DV)*KVR];
__device__ __half hw_o  [HID*NH*DV];
__device__ __half hw_g  [INTER*HID];
__device__ __half hw_u  [INTER*HID];
__device__ __half hw_d  [HID*INTER];

// ---------------- weight fp32 -> fp16 ----------------
__global__ void w2h_kernel(const float* __restrict__ in, __half* __restrict__ out, int n4) {
    int i = blockIdx.x * blockDim.x + threadIdx.x;
    if (i < n4) {
        float4 v = ((const float4*)in)[i];
        __half2 h0 = __floats2half2_rn(v.x, v.y);
        __half2 h1 = __floats2half2_rn(v.z, v.w);
        ((uint2*)out)[i] = make_uint2(*(uint32_t*)&h0, *(uint32_t*)&h1);
    }
}

// ---------------- RMSNorm (fp32 in, fp16 out) ----------------
__global__ void rmsnorm_kernel(const float* __restrict__ in, const float* __restrict__ w,
                               __half* __restrict__ out, int cols, int instride) {
    int row = blockIdx.x;
    int tid = threadIdx.x;
    const float* xr = in + (size_t)row * instride;
    float s = 0.f;
    for (int c = tid; c < cols; c += 256) { float v = xr[c]; s += v * v; }
    __shared__ float red[8];
    for (int o = 16; o; o >>= 1) s += __shfl_xor_sync(0xffffffffu, s, o);
    if ((tid & 31) == 0) red[tid >> 5] = s;
    __syncthreads();
    float tot = 0.f;
    #pragma unroll
    for (int i = 0; i < 8; i++) tot += red[i];
    float inv = rsqrtf(tot / (float)cols + 1e-6f);
    for (int c = tid; c < cols; c += 256)
        out[(size_t)row * cols + c] = __float2half_rn(xr[c] * inv * w[c]);
}

// ---------------- ldmatrix helpers ----------------
__device__ __forceinline__ void ldsm4(uint32_t& r0, uint32_t& r1, uint32_t& r2, uint32_t& r3,
                                      uint32_t addr) {
    asm volatile("ldmatrix.sync.aligned.m8n8.x4.shared.b16 {%0,%1,%2,%3}, [%4];"
                 : "=r"(r0), "=r"(r1), "=r"(r2), "=r"(r3) : "r"(addr));
}
__device__ __forceinline__ void ldsm4t(uint32_t& r0, uint32_t& r1, uint32_t& r2, uint32_t& r3,
                                       uint32_t addr) {
    asm volatile("ldmatrix.sync.aligned.m8n8.x4.trans.shared.b16 {%0,%1,%2,%3}, [%4];"
                 : "=r"(r0), "=r"(r1), "=r"(r2), "=r"(r3) : "r"(addr));
}
#define MMA16816(acc, a0, a1, a2, a3, b0, b1)                                   \
    asm volatile("mma.sync.aligned.m16n8k16.row.col.f32.f16.f16.f32 "           \
                 "{%0,%1,%2,%3}, {%4,%5,%6,%7}, {%8,%9}, {%0,%1,%2,%3};"        \
                 : "+f"((acc)[0]), "+f"((acc)[1]), "+f"((acc)[2]), "+f"((acc)[3]) \
                 : "r"(a0), "r"(a1), "r"(a2), "r"(a3), "r"(b0), "r"(b1))

// ---------------- FP16 mma.sync GEMM (fp32 acc), 3-stage, ldmatrix --------
#define HPITCH 40                          // halves per smem row (80 B)
#define HSTG  (128*HPITCH)
#define GEMM_SMEM (3*2*HSTG*2)
template<int EPI>
__global__ void __launch_bounds__(128, 2)
h16gemm(const __half* __restrict__ A, const __half* __restrict__ W,
        const float* __restrict__ R, float* __restrict__ C,
        int M, int N, int K) {
    extern __shared__ __half smh[];
    const uint32_t sbase = (uint32_t)__cvta_generic_to_shared(smh);

    const int tid  = threadIdx.x;
    const int warp = tid >> 5, lane = tid & 31;
    const int wm = warp >> 1;
    const int wn = warp & 1;
    const int g = lane >> 2, t = lane & 3;
    const int bm = blockIdx.y * 128;
    const int bn = blockIdx.x * 128;

    float acc[4][8][4];
    #pragma unroll
    for (int i = 0; i < 4; i++)
        #pragma unroll
        for (int j = 0; j < 8; j++)
            #pragma unroll
            for (int c = 0; c < 4; c++) acc[i][j][c] = 0.f;

    const int arow = wm * 64 + (lane & 15);
    const int acol = (lane >> 4) << 3;
    const int brow = wn * 64 + ((lane >> 4) << 3) + (lane & 7);
    const int bcol = ((lane >> 3) & 1) << 3;

    auto load_stage = [&](int s, int k0) {
        uint32_t sA = sbase + (uint32_t)(s * 2 * HSTG) * 2;
        uint32_t sW = sA + (uint32_t)HSTG * 2;
        #pragma unroll
        for (int i = 0; i < 4; i++) {
            int ch = tid + 128 * i;
            int m = ch >> 2, c8 = (ch & 3) * 8;
            uint32_t d = sA + (uint32_t)(m * HPITCH + c8) * 2;
            const __half* src = &A[(size_t)(bm + m) * K + k0 + c8];
            asm volatile("cp.async.cg.shared.global [%0], [%1], 16;" :: "r"(d), "l"(src));
            int n = bn + m;
            int ok = (n < N) ? 16 : 0;
            uint32_t dw = sW + (uint32_t)(m * HPITCH + c8) * 2;
            const __half* srcw = &W[(size_t)(n < N ? n : 0) * K + k0 + c8];
            asm volatile("cp.async.cg.shared.global [%0], [%1], 16, %2;"
                         :: "r"(dw), "l"(srcw), "r"(ok));
        }
        asm volatile("cp.async.commit_group;" ::: "memory");
    };

    auto compute = [&](int s) {
        uint32_t sA = sbase + (uint32_t)(s * 2 * HSTG) * 2;
        uint32_t sW = sA + (uint32_t)HSTG * 2;
        #pragma unroll
        for (int ks = 0; ks < 2; ks++) {
            int kk = ks * 16;
            uint32_t af[4][4];
            #pragma unroll
            for (int i = 0; i < 4; i++)
                ldsm4(af[i][0], af[i][1], af[i][2], af[i][3],
                      sA + (uint32_t)((arow + i * 16) * HPITCH + kk + acol) * 2);
            uint32_t bf[8][2];
            #pragma unroll
            for (int jj = 0; jj < 4; jj++)
                ldsm4(bf[2 * jj][0], bf[2 * jj][1], bf[2 * jj + 1][0], bf[2 * jj + 1][1],
                      sW + (uint32_t)((brow + jj * 16) * HPITCH + kk + bcol) * 2);
            #pragma unroll
            for (int i = 0; i < 4; i++)
                #pragma unroll
                for (int j = 0; j < 8; j++)
                    MMA16816(acc[i][j], af[i][0], af[i][1], af[i][2], af[i][3],
                             bf[j][0], bf[j][1]);
        }
    };

    const int NK = K >> 5;
    load_stage(0, 0);
    load_stage(1, 32);

    for (int i = 0; i < NK; i++) {
        if (i + 1 < NK) asm volatile("cp.async.wait_group 1;" ::: "memory");
        else            asm volatile("cp.async.wait_group 0;" ::: "memory");
        __syncthreads();
        if (i + 2 < NK) load_stage((i + 2) % 3, (i + 2) * 32);
        compute(i % 3);
    }

    #pragma unroll
    for (int i = 0; i < 4; i++) {
        int r0 = bm + wm * 64 + i * 16 + g;
        #pragma unroll
        for (int j = 0; j < 8; j++) {
            int c = bn + wn * 64 + j * 8 + 2 * t;
            if (c < N) {
                float2 v0 = make_float2(acc[i][j][0], acc[i][j][1]);
                float2 v1 = make_float2(acc[i][j][2], acc[i][j][3]);
                if (EPI == 1) {
                    float2 r = *(const float2*)&R[(size_t)r0 * N + c];
                    v0.x += r.x; v0.y += r.y;
                    float2 r2 = *(const float2*)&R[(size_t)(r0 + 8) * N + c];
                    v1.x += r2.x; v1.y += r2.y;
                }
                *(float2*)&C[(size_t)r0 * N + c]       = v0;
                *(float2*)&C[(size_t)(r0 + 8) * N + c] = v1;
            }
        }
    }
}

// ---------------- RoPE (yarn) helpers ----------------
__device__ __forceinline__ void yarn_cossin(int j, int pos, float& c, float& s) {
    float ar = (float)j * (1.0f / 32.0f);
    float fe = __powf(10000.0f, -ar);
    float fi = fe * (1.0f / 40.0f);
    float ramp = fminf(fmaxf(((float)j - 10.0f) * (1.0f / 13.0f), 0.0f), 1.0f);
    float f = fi * ramp + fe * (1.0f - ramp);
    float a = (float)pos * f;
    c = cosf(a); s = sinf(a);
}

// q [NTOK, NH*DQ] -> qf fp16 [B,H,S,DQ] with rope on last 64 (deinterleaved)
__global__ void build_qf(const float* __restrict__ q, const int* __restrict__ pos_ids,
                         __half* __restrict__ qf) {
    int t = blockIdx.x;
    int b = t / SEQ, s = t % SEQ;
    int tid = threadIdx.x;              // 128
    __shared__ float cs[32], sn[32];
    int pos = pos_ids[t];
    if (tid < 32) yarn_cossin(tid, pos, cs[tid], sn[tid]);
    __syncthreads();
    for (int h = 0; h < NH; h++) {
        size_t src = (size_t)t * (NH * DQ) + h * DQ;
        size_t dst = ((size_t)(b * NH + h) * SEQ + s) * DQ;
        qf[dst + tid] = __float2half_rn(q[src + tid]);
        if (tid < 32) {
            float p0 = q[src + DNOPE + 2 * tid];
            float p1 = q[src + DNOPE + 2 * tid + 1];
            qf[dst + DNOPE + tid]      = __float2half_rn(p0 * cs[tid] - p1 * sn[tid]);
            qf[dst + DNOPE + 32 + tid] = __float2half_rn(p1 * cs[tid] + p0 * sn[tid]);
        }
    }
}

// kv fp32 [NTOK, NH*256], ckv fp32 -> kf fp16 [B,H,S,192], v fp16 [B,H,S,128]
__global__ void build_kf(const float* __restrict__ kv, const float* __restrict__ ckv,
                         const int* __restrict__ pos_ids,
                         __half* __restrict__ kf, __half* __restrict__ vv) {
    int t = blockIdx.x;
    int b = t / SEQ, s = t % SEQ;
    int tid = threadIdx.x;              // 128
    __shared__ float cs[32], sn[32], kr[64];
    int pos = pos_ids[t];
    if (tid < 32) yarn_cossin(tid, pos, cs[tid], sn[tid]);
    __syncthreads();
    if (tid < 32) {
        float p0 = ckv[(size_t)t * (KVR + DROPE) + KVR + 2 * tid];
        float p1 = ckv[(size_t)t * (KVR + DROPE) + KVR + 2 * tid + 1];
        kr[tid]      = p0 * cs[tid] - p1 * sn[tid];
        kr[tid + 32] = p1 * cs[tid] + p0 * sn[tid];
    }
    __syncthreads();
    for (int h = 0; h < NH; h++) {
        size_t src = (size_t)t * (NH * 256) + h * 256;
        size_t d0 = ((size_t)(b * NH + h) * SEQ + s);
        kf[d0 * DQ + tid] = __float2half_rn(kv[src + tid]);
        vv[d0 * DV + tid] = __float2half_rn(kv[src + DNOPE + tid]);
        if (tid < 64) kf[d0 * DQ + DNOPE + tid] = __float2half_rn(kr[tid]);
    }
}

// ---------------- Tensor-core flash attention ----------------
// CTA: 64 queries (4 warps x 16 rows), key chunks of 64, online softmax.
// S = Q@K^T (m16n8k16), P repacked in-register to A-frags, O += P@V
// (B-frags of V via ldmatrix.trans on row-major V tile).
#define QPITCH 200    // halves (192 data): row stride 400B == 4 banks shift -> conflict-free
#define VPITCH 136    // halves (128 data): row stride 272B == 4 banks shift -> conflict-free
#define ATT_SMEM ((2*64*QPITCH + 64*VPITCH) * 2)
__global__ void __launch_bounds__(128)
attn_tc(const __half* __restrict__ qf, const __half* __restrict__ kf,
        const __half* __restrict__ vv, __half* __restrict__ out) {
    extern __shared__ __half sm[];
    const uint32_t sQ = (uint32_t)__cvta_generic_to_shared(sm);
    const uint32_t sK = sQ + 64 * QPITCH * 2;
    const uint32_t sV = sK + 64 * QPITCH * 2;
    const int tid = threadIdx.x, warp = tid >> 5, lane = tid & 31;
    const int g = lane >> 2, t = lane & 3;
    const int b = blockIdx.z, h = blockIdx.y;
    const int q0 = ((int)gridDim.x - 1 - (int)blockIdx.x) * 64;   // big blocks first
    const __half* Qg = qf + (size_t)(b * NH + h) * SEQ * DQ;
    const __half* Kg = kf + (size_t)(b * NH + h) * SEQ * DQ;
    const __half* Vg = vv + (size_t)(b * NH + h) * SEQ * DV;
    const int wrow = warp * 16;
    const float scale = 0.07216878364870323f;    // 192^-0.5

    // Q tile 64x192
    #pragma unroll
    for (int i = 0; i < 12; i++) {
        int ch = tid + 128 * i;
        int r = ch / 24, c = (ch % 24) * 8;
        uint32_t d = sQ + (uint32_t)(r * QPITCH + c) * 2;
        const __half* src = Qg + (size_t)(q0 + r) * DQ + c;
        asm volatile("cp.async.cg.shared.global [%0], [%1], 16;" :: "r"(d), "l"(src));
    }
    asm volatile("cp.async.commit_group;" ::: "memory");

    float o[16][4];
    #pragma unroll
    for (int i = 0; i < 16; i++)
        #pragma unroll
        for (int c = 0; c < 4; c++) o[i][c] = 0.f;
    float m0 = -INFINITY, m1 = -INFINITY, l0 = 0.f, l1 = 0.f;

    const uint32_t aoff = (uint32_t)((wrow + (lane & 15)) * QPITCH + ((lane >> 4) << 3)) * 2;
    const int brow = ((lane >> 4) << 3) + (lane & 7);
    const int bcol = ((lane >> 3) & 1) << 3;
    const int vrow = lane & 15;
    const int vcol = ((lane >> 4) << 3);

    for (int kc = 0; kc <= q0; kc += 64) {
        __syncthreads();   // prior chunk's compute done before overwriting K/V
        #pragma unroll
        for (int i = 0; i < 12; i++) {
            int ch = tid + 128 * i;
            int r = ch / 24, c = (ch % 24) * 8;
            uint32_t d = sK + (uint32_t)(r * QPITCH + c) * 2;
            const __half* src = Kg + (size_t)(kc + r) * DQ + c;
            asm volatile("cp.async.cg.shared.global [%0], [%1], 16;" :: "r"(d), "l"(src));
        }
        #pragma unroll
        for (int i = 0; i < 8; i++) {
            int ch = tid + 128 * i;
            int r = ch / 16, c = (ch % 16) * 8;
            uint32_t d = sV + (uint32_t)(r * VPITCH + c) * 2;
            const __half* src = Vg + (size_t)(kc + r) * DV + c;
            asm volatile("cp.async.cg.shared.global [%0], [%1], 16;" :: "r"(d), "l"(src));
        }
        asm volatile("cp.async.commit_group;" ::: "memory");
        asm volatile("cp.async.wait_group 0;" ::: "memory");
        __syncthreads();

        // ---- S = Q @ K^T ----
        float sacc[8][4];
        #pragma unroll
        for (int nt = 0; nt < 8; nt++)
            #pragma unroll
            for (int c = 0; c < 4; c++) sacc[nt][c] = 0.f;
        #pragma unroll
        for (int kt = 0; kt < 12; kt++) {
            uint32_t a0, a1, a2, a3;
            ldsm4(a0, a1, a2, a3, sQ + aoff + kt * 32);
            uint32_t bf[8][2];
            #pragma unroll
            for (int jj = 0; jj < 4; jj++)
                ldsm4(bf[2 * jj][0], bf[2 * jj][1], bf[2 * jj + 1][0], bf[2 * jj + 1][1],
                      sK + (uint32_t)((jj * 16 + brow) * QPITCH + kt * 16 + bcol) * 2);
            #pragma unroll
            for (int nt = 0; nt < 8; nt++)
                MMA16816(sacc[nt], a0, a1, a2, a3, bf[nt][0], bf[nt][1]);
        }
        // scale + causal mask (only diagonal chunk)
        int r0w = q0 + wrow + g, r1w = r0w + 8;
        #pragma unroll
        for (int nt = 0; nt < 8; nt++)
            #pragma unroll
            for (int c = 0; c < 4; c++) sacc[nt][c] *= scale;
        if (kc == q0) {
            #pragma unroll
            for (int nt = 0; nt < 8; nt++) {
                int c0 = kc + nt * 8 + 2 * t;
                if (c0     > r0w) sacc[nt][0] = -INFINITY;
                if (c0 + 1 > r0w) sacc[nt][1] = -INFINITY;
                if (c0     > r1w) sacc[nt][2] = -INFINITY;
                if (c0 + 1 > r1w) sacc[nt][3] = -INFINITY;
            }
        }
        // ---- online softmax (rows g, g+8) ----
        float mx0 = -INFINITY, mx1 = -INFINITY;
        #pragma unroll
        for (int nt = 0; nt < 8; nt++) {
            mx0 = fmaxf(mx0, fmaxf(sacc[nt][0], sacc[nt][1]));
            mx1 = fmaxf(mx1, fmaxf(sacc[nt][2], sacc[nt][3]));
        }
        mx0 = fmaxf(mx0, __shfl_xor_sync(0xffffffffu, mx0, 1));
        mx0 = fmaxf(mx0, __shfl_xor_sync(0xffffffffu, mx0, 2));
        mx1 = fmaxf(mx1, __shfl_xor_sync(0xffffffffu, mx1, 1));
        mx1 = fmaxf(mx1, __shfl_xor_sync(0xffffffffu, mx1, 2));
        float nm0 = fmaxf(m0, mx0), nm1 = fmaxf(m1, mx1);
        float cf0 = __expf(m0 - nm0), cf1 = __expf(m1 - nm1);
        float s0 = 0.f, s1 = 0.f;
        uint32_t ph01[8], ph23[8];
        #pragma unroll
        for (int nt = 0; nt < 8; nt++) {
            float p0 = __expf(sacc[nt][0] - nm0);
            float p1 = __expf(sacc[nt][1] - nm0);
            float p2 = __expf(sacc[nt][2] - nm1);
            float p3 = __expf(sacc[nt][3] - nm1);
            s0 += p0 + p1; s1 += p2 + p3;
            __half2 q01 = __floats2half2_rn(p0, p1);
            __half2 q23 = __floats2half2_rn(p2, p3);
            ph01[nt] = *(uint32_t*)&q01;
            ph23[nt] = *(uint32_t*)&q23;
        }
        s0 += __shfl_xor_sync(0xffffffffu, s0, 1);
        s0 += __shfl_xor_sync(0xffffffffu, s0, 2);
        s1 += __shfl_xor_sync(0xffffffffu, s1, 1);
        s1 += __shfl_xor_sync(0xffffffffu, s1, 2);
        l0 = l0 * cf0 + s0;
        l1 = l1 * cf1 + s1;
        m0 = nm0; m1 = nm1;
        #pragma unroll
        for (int nv = 0; nv < 16; nv++) {
            o[nv][0] *= cf0; o[nv][1] *= cf0;
            o[nv][2] *= cf1; o[nv][3] *= cf1;
        }
        // ---- O += P @ V ----
        #pragma unroll
        for (int kt2 = 0; kt2 < 4; kt2++) {
            uint32_t a0 = ph01[2 * kt2], a1 = ph23[2 * kt2];
            uint32_t a2 = ph01[2 * kt2 + 1], a3 = ph23[2 * kt2 + 1];
            #pragma unroll
            for (int jv = 0; jv < 8; jv++) {
                uint32_t b0, b1, b2, b3;
                ldsm4t(b0, b1, b2, b3,
                       sV + (uint32_t)((kt2 * 16 + vrow) * VPITCH + jv * 16 + vcol) * 2);
                MMA16816(o[2 * jv],     a0, a1, a2, a3, b0, b1);
                MMA16816(o[2 * jv + 1], a0, a1, a2, a3, b2, b3);
            }
        }
    }

    // ---- write O (fp16, [tok][NH*DV]) ----
    float inv0 = 1.f / l0, inv1 = 1.f / l1;
    int r0w = q0 + wrow + g, r1w = r0w + 8;
    #pragma unroll
    for (int nv = 0; nv < 16; nv++) {
        int col = nv * 8 + 2 * t;
        __half2 v0 = __floats2half2_rn(o[nv][0] * inv0, o[nv][1] * inv0);
        __half2 v1 = __floats2half2_rn(o[nv][2] * inv1, o[nv][3] * inv1);
        *(__half2*)&out[(size_t)(b * SEQ + r0w) * (NH * DV) + h * DV + col] = v0;
        *(__half2*)&out[(size_t)(b * SEQ + r1w) * (NH * DV) + h * DV + col] = v1;
    }
}

// ---------------- SiLU(g)*u -> fp16 (feeds Wd GEMM) ----------------------
__global__ void silu_mul(const float* __restrict__ g, const float* __restrict__ u,
                         __half* __restrict__ o, size_t n) {
    for (size_t i = (size_t)blockIdx.x * blockDim.x + threadIdx.x; i < n;
         i += (size_t)gridDim.x * blockDim.x) {
        float x = g[i];
        o[i] = __float2half_rn(x / (1.0f + __expf(-x)) * u[i]);
    }
}

// ---------------- Launch ----------------
extern "C" void kernel_launch(void* const* d_in, const int* in_sizes, int n_in,
                              void* d_out, int out_size) {
    const float* hidden = (const float*)d_in[0];
    const int*   pos    = (const int*)d_in[1];
    const float* Wq     = (const float*)d_in[2];
    const float* Wkva   = (const float*)d_in[3];
    const float* w_kvln = (const float*)d_in[4];
    const float* Wkvb   = (const float*)d_in[5];
    const float* Wo     = (const float*)d_in[6];
    const float* Wg     = (const float*)d_in[7];
    const float* Wu     = (const float*)d_in[8];
    const float* Wd     = (const float*)d_in[9];
    const float* w_ln1  = (const float*)d_in[10];
    const float* w_ln2  = (const float*)d_in[11];
    float* out = (float*)d_out;

    __half *xln, *cln, *attn, *yh, *gh, *qfp, *kfp, *vp;
    __half *wq, *wkva, *wkvb, *wo, *wg, *wu, *wd;
    float *q, *ckv, *kv, *x1, *gg, *uu;
    cudaGetSymbolAddress((void**)&xln,  h_xln);
    cudaGetSymbolAddress((void**)&cln,  h_cln);
    cudaGetSymbolAddress((void**)&attn, h_attn);
    cudaGetSymbolAddress((void**)&yh,   h_y);
    cudaGetSymbolAddress((void**)&gh,   h_gh);
    cudaGetSymbolAddress((void**)&qfp,  h_qf);
    cudaGetSymbolAddress((void**)&kfp,  h_kf);
    cudaGetSymbolAddress((void**)&vp,   h_v);
    cudaGetSymbolAddress((void**)&wq,   hw_q);
    cudaGetSymbolAddress((void**)&wkva, hw_kva);
    cudaGetSymbolAddress((void**)&wkvb, hw_kvb);
    cudaGetSymbolAddress((void**)&wo,   hw_o);
    cudaGetSymbolAddress((void**)&wg,   hw_g);
    cudaGetSymbolAddress((void**)&wu,   hw_u);
    cudaGetSymbolAddress((void**)&wd,   hw_d);
    cudaGetSymbolAddress((void**)&q,    g_q);
    cudaGetSymbolAddress((void**)&ckv,  g_ckv);
    cudaGetSymbolAddress((void**)&kv,   g_kv);
    cudaGetSymbolAddress((void**)&x1,   g_x1);
    cudaGetSymbolAddress((void**)&gg,   g_g);
    cudaGetSymbolAddress((void**)&uu,   g_u);

    cudaFuncSetAttribute(h16gemm<0>, cudaFuncAttributeMaxDynamicSharedMemorySize, GEMM_SMEM);
    cudaFuncSetAttribute(h16gemm<1>, cudaFuncAttributeMaxDynamicSharedMemorySize, GEMM_SMEM);
    cudaFuncSetAttribute(attn_tc, cudaFuncAttributeMaxDynamicSharedMemorySize, ATT_SMEM);

    dim3 blk(256);
    // 0. weights -> fp16
    {
        struct { const float* s; __half* d; int n; } ws[7] = {
            {Wq,   wq,   NH*DQ*HID}, {Wkva, wkva, (KVR+DROPE)*HID},
            {Wkvb, wkvb, NH*(DNOPE+DV)*KVR}, {Wo, wo, HID*NH*DV},
            {Wg,   wg,   INTER*HID}, {Wu, wu, INTER*HID}, {Wd, wd, HID*INTER}
        };
        for (int i = 0; i < 7; i++) {
            int n4 = ws[i].n / 4;
            w2h_kernel<<<(n4 + 255) / 256, 256>>>(ws[i].s, ws[i].d, n4);
        }
    }
    // 1. ln1 (fp16 out)
    rmsnorm_kernel<<<NTOK, blk>>>(hidden, w_ln1, xln, HID, HID);
    // 2. q = xln @ Wq^T   [4096 x 3072] K=2048
    h16gemm<0><<<dim3(24, 32), 128, GEMM_SMEM>>>(xln, wq, nullptr, q, NTOK, NH * DQ, HID);
    // 3. ckv = xln @ Wkva^T  [4096 x 576] K=2048
    h16gemm<0><<<dim3(5, 32), 128, GEMM_SMEM>>>(xln, wkva, nullptr, ckv, NTOK, KVR + DROPE, HID);
    // 4. c_ln = rms(ckv[:, :512]) * w_kvln (fp16 out)
    rmsnorm_kernel<<<NTOK, blk>>>(ckv, w_kvln, cln, KVR, KVR + DROPE);
    // 5. kv = c_ln @ Wkvb^T  [4096 x 4096] K=512
    h16gemm<0><<<dim3(32, 32), 128, GEMM_SMEM>>>(cln, wkvb, nullptr, kv, NTOK, NH * 256, KVR);
    // 6/7. layouts + rope (fp16 out)
    build_qf<<<NTOK, 128>>>(q, pos, qfp);
    build_kf<<<NTOK, 128>>>(kv, ckv, pos, kfp, vp);
    // 8. tensor-core flash attention (fp16 out)
    attn_tc<<<dim3(SEQ / 64, NH, BATCH), 128, ATT_SMEM>>>(qfp, kfp, vp, attn);
    // 9. x1 = hidden + attn @ Wo^T  K=2048
    h16gemm<1><<<dim3(16, 32), 128, GEMM_SMEM>>>(attn, wo, hidden, x1, NTOK, HID, NH * DV);
    // 10. y = rms(x1) * w_ln2 (fp16 out)
    rmsnorm_kernel<<<NTOK, blk>>>(x1, w_ln2, yh, HID, HID);
    // 11. g = y @ Wg^T, u = y @ Wu^T  [4096 x 10944] K=2048
    h16gemm<0><<<dim3(86, 32), 128, GEMM_SMEM>>>(yh, wg, nullptr, gg, NTOK, INTER, HID);
    h16gemm<0><<<dim3(86, 32), 128, GEMM_SMEM>>>(yh, wu, nullptr, uu, NTOK, INTER, HID);
    // 12. gh = silu(g) * u (fp16 out)
    silu_mul<<<4096, blk>>>(gg, uu, gh, (size_t)NTOK * INTER);
    // 13. out = x1 + gh @ Wd^T  K=10944
    h16gemm<1><<<dim3(16, 32), 128, GEMM_SMEM>>>(gh, wd, x1, out, NTOK, HID, INTER);
}